// round 14
// baseline (speedup 1.0000x reference)
#include <cuda_runtime.h>
#include <cuda_bf16.h>
#include <cstdint>

#define BB   8
#define NPTS 8192
#define SPTS 2048
#define D1C  128
#define D2C  256
#define INCH 384
#define C1   256
#define C2   128
#define NPART 512
#define SSPLIT 4
#define SCHUNK (SPTS / SSPLIT)   // 512

// ===================== PTX helpers (standard sm_80+ ISA only) ===============
__device__ __forceinline__ uint32_t smem_u32(const void* p) {
    uint32_t a;
    asm("{ .reg .u64 t; cvta.to.shared.u64 t, %1; cvt.u32.u64 %0, t; }" : "=r"(a) : "l"(p));
    return a;
}
#define CP16(dst, src) \
    asm volatile("cp.async.cg.shared.global [%0], [%1], 16;" :: "r"(dst), "l"(src))
#define CP_COMMIT() asm volatile("cp.async.commit_group;" ::: "memory")
#define CP_WAIT0()  asm volatile("cp.async.wait_group 0;" ::: "memory")
#define CP_WAIT1()  asm volatile("cp.async.wait_group 1;" ::: "memory")

__device__ __forceinline__ void ldm4(uint32_t* r, uint32_t addr) {
    asm volatile("ldmatrix.sync.aligned.m8n8.x4.shared.b16 {%0,%1,%2,%3}, [%4];"
                 : "=r"(r[0]), "=r"(r[1]), "=r"(r[2]), "=r"(r[3]) : "r"(addr));
}
__device__ __forceinline__ void mma16816(float* c, const uint32_t* a, const uint32_t* b) {
    asm volatile("mma.sync.aligned.m16n8k16.row.col.f32.bf16.bf16.f32 "
                 "{%0,%1,%2,%3}, {%4,%5,%6,%7}, {%8,%9}, {%0,%1,%2,%3};"
                 : "+f"(c[0]), "+f"(c[1]), "+f"(c[2]), "+f"(c[3])
                 : "r"(a[0]), "r"(a[1]), "r"(a[2]), "r"(a[3]), "r"(b[0]), "r"(b[1]));
}
__device__ __forceinline__ void split_bf16(float x, __nv_bfloat16& h, __nv_bfloat16& l) {
    h = __float2bfloat16_rn(x);
    l = __float2bfloat16_rn(x - __bfloat162float(h));
}
__device__ __forceinline__ void pack_split2(float v0, float v1, uint32_t& hw, uint32_t& lw) {
    __nv_bfloat16 h0, l0, h1, l1;
    split_bf16(v0, h0, l0); split_bf16(v1, h1, l1);
    hw = (uint32_t)__bfloat16_as_ushort(h0) | ((uint32_t)__bfloat16_as_ushort(h1) << 16);
    lw = (uint32_t)__bfloat16_as_ushort(l0) | ((uint32_t)__bfloat16_as_ushort(l1) << 16);
}

// ===================== scratch ==============================================
__device__ int   g_idx[BB * NPTS * 3];
__device__ float g_w[BB * NPTS * 3];
__device__ float g_pd[BB * SSPLIT * 3 * NPTS];   // [b][z][t][n] coalesced
__device__ int   g_pi[BB * SSPLIT * 3 * NPTS];

__device__ __nv_bfloat16 g_W0ah[C1 * D1C], g_W0al[C1 * D1C];
__device__ __nv_bfloat16 g_W0bh[C1 * D2C], g_W0bl[C1 * D2C];
__device__ __nv_bfloat16 g_W1h[C2 * C1],   g_W1l[C2 * C1];
__device__ __nv_bfloat16 g_P1h[BB * NPTS * D1C], g_P1l[BB * NPTS * D1C];
__device__ __nv_bfloat16 g_P2h[BB * SPTS * D2C], g_P2l[BB * SPTS * D2C];

__device__ float g_Zt[BB * SPTS * C1];     // [b][s][o]
__device__ float g_Y1[BB * NPTS * C1];     // [b][n][o] fp32
__device__ float g_Y2[BB * NPTS * C2];     // [b][n][o]
__device__ float g_p1s[C1 * NPART], g_p1q[C1 * NPART];
__device__ float g_p2s[C2 * NPART], g_p2q[C2 * NPART];
__device__ float g_a0[C1], g_c0[C1], g_a1[C2], g_c1[C2];

// ===================== 1a) 3-NN partial scan (2 query pts / thread) =========
__global__ void knn_part(const float* __restrict__ xyz1,
                         const float* __restrict__ xyz2) {
    __shared__ float4 s2[SCHUNK];
    const int b = blockIdx.y, z = blockIdx.z;
    const int tid = threadIdx.x;
    const int s0 = z * SCHUNK;
    for (int s = tid; s < SCHUNK; s += 256) {
        float x = xyz2[(b * 3 + 0) * SPTS + s0 + s];
        float y = xyz2[(b * 3 + 1) * SPTS + s0 + s];
        float zz = xyz2[(b * 3 + 2) * SPTS + s0 + s];
        s2[s] = make_float4(x, y, zz, x * x + y * y + zz * zz);
    }
    __syncthreads();
    const int nA = blockIdx.x * 512 + tid;
    const int nB = nA + 256;
    const float pxA = xyz1[(b * 3 + 0) * NPTS + nA];
    const float pyA = xyz1[(b * 3 + 1) * NPTS + nA];
    const float pzA = xyz1[(b * 3 + 2) * NPTS + nA];
    const float n1A = pxA * pxA + pyA * pyA + pzA * pzA;
    const float pxB = xyz1[(b * 3 + 0) * NPTS + nB];
    const float pyB = xyz1[(b * 3 + 1) * NPTS + nB];
    const float pzB = xyz1[(b * 3 + 2) * NPTS + nB];
    const float n1B = pxB * pxB + pyB * pyB + pzB * pzB;
    float a0 = 3.4e38f, a1 = 3.4e38f, a2 = 3.4e38f;
    float b0 = 3.4e38f, b1 = 3.4e38f, b2 = 3.4e38f;
    int   ia0 = 0, ia1 = 0, ia2 = 0, ib0 = 0, ib1 = 0, ib2 = 0;
#pragma unroll 4
    for (int s = 0; s < SCHUNK; s++) {
        float4 q = s2[s];
        float dA = n1A + q.w - 2.f * (pxA * q.x + pyA * q.y + pzA * q.z);
        float dB = n1B + q.w - 2.f * (pxB * q.x + pyB * q.y + pzB * q.z);
        if (dA < a2) {
            if (dA < a1) {
                a2 = a1; ia2 = ia1;
                if (dA < a0) { a1 = a0; ia1 = ia0; a0 = dA; ia0 = s0 + s; }
                else         { a1 = dA; ia1 = s0 + s; }
            } else { a2 = dA; ia2 = s0 + s; }
        }
        if (dB < b2) {
            if (dB < b1) {
                b2 = b1; ib2 = ib1;
                if (dB < b0) { b1 = b0; ib1 = ib0; b0 = dB; ib0 = s0 + s; }
                else         { b1 = dB; ib1 = s0 + s; }
            } else { b2 = dB; ib2 = s0 + s; }
        }
    }
    {
        const int base = (b * SSPLIT + z) * 3 * NPTS + nA;
        g_pd[base] = a0; g_pd[base + NPTS] = a1; g_pd[base + 2 * NPTS] = a2;
        g_pi[base] = ia0; g_pi[base + NPTS] = ia1; g_pi[base + 2 * NPTS] = ia2;
    }
    {
        const int base = (b * SSPLIT + z) * 3 * NPTS + nB;
        g_pd[base] = b0; g_pd[base + NPTS] = b1; g_pd[base + 2 * NPTS] = b2;
        g_pi[base] = ib0; g_pi[base + NPTS] = ib1; g_pi[base + 2 * NPTS] = ib2;
    }
}

// ===================== 1b) 3-NN merge + weights =============================
__global__ void knn_merge() {
    const int g = blockIdx.x * 256 + threadIdx.x;    // b*NPTS + n
    const int b = g / NPTS, n = g % NPTS;
    float d0 = 3.4e38f, d1 = 3.4e38f, d2 = 3.4e38f;
    int   i0 = 0, i1 = 0, i2 = 0;
#pragma unroll
    for (int z = 0; z < SSPLIT; z++) {
#pragma unroll
        for (int t = 0; t < 3; t++) {
            const int base = ((b * SSPLIT + z) * 3 + t) * NPTS + n;
            const float d = g_pd[base];
            const int   s = g_pi[base];
            if (d < d2) {
                if (d < d1) {
                    d2 = d1; i2 = i1;
                    if (d < d0) { d1 = d0; i1 = i0; d0 = d; i0 = s; }
                    else        { d1 = d;  i1 = s; }
                } else { d2 = d; i2 = s; }
            }
        }
    }
    const float r0 = 1.f / (d0 + 1e-8f);
    const float r1 = 1.f / (d1 + 1e-8f);
    const float r2 = 1.f / (d2 + 1e-8f);
    const float inv = 1.f / (r0 + r1 + r2);
    g_idx[g * 3 + 0] = i0; g_idx[g * 3 + 1] = i1; g_idx[g * 3 + 2] = i2;
    g_w[g * 3 + 0] = r0 * inv; g_w[g * 3 + 1] = r1 * inv; g_w[g * 3 + 2] = r2 * inv;
}

// ===================== 2) weight split ======================================
__global__ void conv_w(const float* __restrict__ W0, const float* __restrict__ W1) {
    const int idx = blockIdx.x * 256 + threadIdx.x;
    if (idx < C1 * INCH) {
        const int o = idx / INCH, k = idx % INCH;
        __nv_bfloat16 h, l;
        split_bf16(W0[idx], h, l);
        if (k < D1C) { g_W0ah[o * D1C + k] = h; g_W0al[o * D1C + k] = l; }
        else         { g_W0bh[o * D2C + k - D1C] = h; g_W0bl[o * D2C + k - D1C] = l; }
    } else {
        const int j = idx - C1 * INCH;
        if (j < C2 * C1) { __nv_bfloat16 h, l; split_bf16(W1[j], h, l); g_W1h[j] = h; g_W1l[j] = l; }
    }
}

// ===================== 3) activation transpose + split (vectorized) =========
template <int DD, int NTOT>
__global__ void conv_t(const float* __restrict__ in, __nv_bfloat16* __restrict__ oh,
                       __nv_bfloat16* __restrict__ ol) {
    __shared__ float t[64][33];
    const int b = blockIdx.z;
    const int n0 = blockIdx.x * 32, d0 = blockIdx.y * 64;
    const int tx = threadIdx.x, ty = threadIdx.y;
#pragma unroll
    for (int i = 0; i < 8; i++)
        t[ty + 8 * i][tx] = in[((size_t)b * DD + d0 + ty + 8 * i) * NTOT + n0 + tx];
    __syncthreads();
#pragma unroll
    for (int i = 0; i < 4; i++) {
        const int n = n0 + ty + 8 * i;
        const float v0 = t[2 * tx][ty + 8 * i];
        const float v1 = t[2 * tx + 1][ty + 8 * i];
        uint32_t hw, lw;
        pack_split2(v0, v1, hw, lw);
        const size_t off = (((size_t)b * NTOT + n) * DD + d0) / 2 + tx;
        ((uint32_t*)oh)[off] = hw;
        ((uint32_t*)ol)[off] = lw;
    }
}

#define TILEB 10240          // 128 rows * 80 bytes (32 bf16 + 8 pad)
#define BUFSZ (4 * TILEB)

// ===================== 4a) mma.sync GEMM (bf16 pre-split A via cp.async) ====
// MODE 0: plain fp32 store (Zt). MODE 1: +bias +3-NN gather, BN partials.
template <int NOUT, int KIN, int MODE, int NTOT>
__global__ void __launch_bounds__(256, 2) gemm_mma(
    const __nv_bfloat16* __restrict__ Ah, const __nv_bfloat16* __restrict__ Al,
    const __nv_bfloat16* __restrict__ Bh, const __nv_bfloat16* __restrict__ Bl,
    const float* __restrict__ bias, float* __restrict__ out,
    float* __restrict__ ps, float* __restrict__ pq)
{
    constexpr int NCH = KIN / 32;
    extern __shared__ char sm[];
    const uint32_t sbase = smem_u32(sm);
    int*   sIdx = (int*)(sm + 2 * BUFSZ);
    float* sW   = (float*)(sm + 2 * BUFSZ + 1536);
    float* sPs  = (float*)(sm + 2 * BUFSZ + 3072);
    float* sPq  = sPs + 256;

    const int tid  = threadIdx.x;
    const int lane = tid & 31, wid = tid >> 5;
    const int wm = wid >> 2, wn = wid & 3;
    const int m0w = wm * 64, n0w = wn * 32;
    const int b    = blockIdx.y;
    const int mblk = blockIdx.x * 128;
    const int oblk = blockIdx.z * 128;
    const size_t bRow0 = (size_t)b * NTOT + mblk;

    if (MODE == 1 && tid < 128) {
        const int gi = (b * NPTS + mblk + tid) * 3;
#pragma unroll
        for (int t = 0; t < 3; t++) { sIdx[tid * 3 + t] = g_idx[gi + t]; sW[tid * 3 + t] = g_w[gi + t]; }
    }

    const int ldRow = tid >> 1;
    const int ldSeg = (tid & 1) * 2;

    const uint32_t aOff = (uint32_t)(m0w + (lane & 15)) * 80 + (uint32_t)(lane >> 4) * 16;
    const uint32_t bOff = (uint32_t)(n0w + ((lane >> 4) << 3) + (lane & 7)) * 80 +
                          (uint32_t)((lane >> 3) & 1) * 16;

    float acc[4][4][4] = {};

    auto load_chunk = [&](int c, int buf) {
        const int koff = c * 32;
        const uint32_t dA = sbase + buf * BUFSZ + ldRow * 80 + ldSeg * 16;
        const char* sAh = (const char*)(Ah + (bRow0 + ldRow) * KIN + koff) + ldSeg * 16;
        const char* sAl = (const char*)(Al + (bRow0 + ldRow) * KIN + koff) + ldSeg * 16;
        const char* sBh = (const char*)(Bh + (size_t)(oblk + ldRow) * KIN + koff) + ldSeg * 16;
        const char* sBl = (const char*)(Bl + (size_t)(oblk + ldRow) * KIN + koff) + ldSeg * 16;
        CP16(dA,             sAh);      CP16(dA + 16,             sAh + 16);
        CP16(dA + TILEB,     sAl);      CP16(dA + TILEB + 16,     sAl + 16);
        CP16(dA + 2 * TILEB, sBh);      CP16(dA + 2 * TILEB + 16, sBh + 16);
        CP16(dA + 3 * TILEB, sBl);      CP16(dA + 3 * TILEB + 16, sBl + 16);
    };

    load_chunk(0, 0);
    CP_COMMIT();

    int buf = 0;
    for (int c = 0; c < NCH; c++) {
        if (c + 1 < NCH) { load_chunk(c + 1, buf ^ 1); CP_COMMIT(); CP_WAIT1(); }
        else             { CP_WAIT0(); }
        __syncthreads();
        const uint32_t aHb = sbase + buf * BUFSZ;
#pragma unroll
        for (int ks = 0; ks < 2; ks++) {
            const uint32_t kb = ks * 32;
            uint32_t bh[4][2], bl[4][2];
            {
                uint32_t t4[4];
                ldm4(t4, aHb + 2 * TILEB + bOff + kb);
                bh[0][0] = t4[0]; bh[0][1] = t4[1]; bh[1][0] = t4[2]; bh[1][1] = t4[3];
                ldm4(t4, aHb + 2 * TILEB + bOff + kb + 16 * 80);
                bh[2][0] = t4[0]; bh[2][1] = t4[1]; bh[3][0] = t4[2]; bh[3][1] = t4[3];
                ldm4(t4, aHb + 3 * TILEB + bOff + kb);
                bl[0][0] = t4[0]; bl[0][1] = t4[1]; bl[1][0] = t4[2]; bl[1][1] = t4[3];
                ldm4(t4, aHb + 3 * TILEB + bOff + kb + 16 * 80);
                bl[2][0] = t4[0]; bl[2][1] = t4[1]; bl[3][0] = t4[2]; bl[3][1] = t4[3];
            }
#pragma unroll
            for (int i = 0; i < 4; i++) {
                uint32_t ah[4], al[4];
                ldm4(ah, aHb + aOff + kb + i * 16 * 80);
                ldm4(al, aHb + TILEB + aOff + kb + i * 16 * 80);
#pragma unroll
                for (int j = 0; j < 4; j++) {
                    mma16816(acc[i][j], ah, bh[j]);
                    mma16816(acc[i][j], al, bh[j]);
                    mma16816(acc[i][j], ah, bl[j]);
                }
            }
        }
        __syncthreads();
        buf ^= 1;
    }

    // ------------- epilogue -------------
    float2 bias2[4];
    if (MODE >= 1) {
#pragma unroll
        for (int j = 0; j < 4; j++)
            bias2[j] = *(const float2*)&bias[oblk + n0w + 8 * j + 2 * (lane & 3)];
    }
    float sc[8] = {}, qc[8] = {};
#pragma unroll
    for (int i = 0; i < 4; i++) {
#pragma unroll
        for (int s = 0; s < 2; s++) {
            const int rl = m0w + 16 * i + 8 * s + (lane >> 2);
            float* orow = out + (bRow0 + rl) * NOUT;
            const float *z0 = nullptr, *z1 = nullptr, *z2 = nullptr;
            float w0 = 0.f, w1 = 0.f, w2 = 0.f;
            if (MODE == 1) {
                z0 = g_Zt + ((size_t)b * SPTS + sIdx[rl * 3 + 0]) * C1;
                z1 = g_Zt + ((size_t)b * SPTS + sIdx[rl * 3 + 1]) * C1;
                z2 = g_Zt + ((size_t)b * SPTS + sIdx[rl * 3 + 2]) * C1;
                w0 = sW[rl * 3 + 0]; w1 = sW[rl * 3 + 1]; w2 = sW[rl * 3 + 2];
            }
#pragma unroll
            for (int j = 0; j < 4; j++) {
                const int col = oblk + n0w + 8 * j + 2 * (lane & 3);
                float v0 = acc[i][j][2 * s], v1 = acc[i][j][2 * s + 1];
                if (MODE >= 1) { v0 += bias2[j].x; v1 += bias2[j].y; }
                if (MODE == 1) {
                    float2 za = *(const float2*)(z0 + col);
                    float2 zb = *(const float2*)(z1 + col);
                    float2 zc = *(const float2*)(z2 + col);
                    v0 += w0 * za.x + w1 * zb.x + w2 * zc.x;
                    v1 += w0 * za.y + w1 * zb.y + w2 * zc.y;
                    sc[2 * j] += v0;     qc[2 * j] = fmaf(v0, v0, qc[2 * j]);
                    sc[2 * j + 1] += v1; qc[2 * j + 1] = fmaf(v1, v1, qc[2 * j + 1]);
                }
                *(float2*)(orow + col) = make_float2(v0, v1);
            }
        }
    }
    if (MODE == 1) {
#pragma unroll
        for (int k = 0; k < 8; k++) {
#pragma unroll
            for (int off = 16; off >= 4; off >>= 1) {
                sc[k] += __shfl_down_sync(0xffffffffu, sc[k], off);
                qc[k] += __shfl_down_sync(0xffffffffu, qc[k], off);
            }
        }
        if (lane < 4) {
#pragma unroll
            for (int j = 0; j < 4; j++) {
                const int cl = n0w + 8 * j + 2 * lane;
                sPs[wm * 128 + cl] = sc[2 * j];         sPq[wm * 128 + cl] = qc[2 * j];
                sPs[wm * 128 + cl + 1] = sc[2 * j + 1]; sPq[wm * 128 + cl + 1] = qc[2 * j + 1];
            }
        }
        __syncthreads();
        if (tid < 128) {
            const float S = sPs[tid] + sPs[128 + tid];
            const float Q = sPq[tid] + sPq[128 + tid];
            const int slot = (oblk + tid) * NPART + b * 64 + blockIdx.x;
            ps[slot] = S; pq[slot] = Q;
        }
    }
}

// ===================== 4b) layer-2 GEMM: fp32 Y1 staging + BN + relu ========
__global__ void __launch_bounds__(256, 2) gemm_y2(
    const float* __restrict__ Y1, const __nv_bfloat16* __restrict__ Bh,
    const __nv_bfloat16* __restrict__ Bl, const float* __restrict__ bias,
    float* __restrict__ out, float* __restrict__ ps, float* __restrict__ pq)
{
    constexpr int NCH = C1 / 32;       // 8
    extern __shared__ char sm[];
    const uint32_t sbase = smem_u32(sm);
    float* sA0 = (float*)(sm + 2 * BUFSZ);            // [256]
    float* sC0 = sA0 + 256;
    float* sPs = sC0 + 256;                           // [2][128]
    float* sPq = sPs + 256;

    const int tid  = threadIdx.x;
    const int lane = tid & 31, wid = tid >> 5;
    const int wm = wid >> 2, wn = wid & 3;
    const int m0w = wm * 64, n0w = wn * 32;
    const int b    = blockIdx.y;
    const int mblk = blockIdx.x * 128;
    const size_t bRow0 = (size_t)b * NPTS + mblk;

    sA0[tid] = g_a0[tid];
    sC0[tid] = g_c0[tid];

    const int ldRow = tid >> 1;
    const int ldSeg = (tid & 1) * 2;         // for B cp.async (2x16B)
    const int aCol0 = (tid & 1) * 16;        // 16 fp32 per thread for A

    const uint32_t aOff = (uint32_t)(m0w + (lane & 15)) * 80 + (uint32_t)(lane >> 4) * 16;
    const uint32_t bOff = (uint32_t)(n0w + ((lane >> 4) << 3) + (lane & 7)) * 80 +
                          (uint32_t)((lane >> 3) & 1) * 16;

    float acc[4][4][4] = {};
    float4 rA[4];

    auto ldgA = [&](int c) {
        const float* src = Y1 + (bRow0 + ldRow) * C1 + c * 32 + aCol0;
#pragma unroll
        for (int i = 0; i < 4; i++) rA[i] = __ldg((const float4*)(src + 4 * i));
    };
    auto cpB = [&](int c, int bf) {
        const int koff = c * 32;
        const uint32_t dB = sbase + bf * BUFSZ + 2 * TILEB + ldRow * 80 + ldSeg * 16;
        const char* sBh = (const char*)(Bh + (size_t)ldRow * C1 + koff) + ldSeg * 16;
        const char* sBl = (const char*)(Bl + (size_t)ldRow * C1 + koff) + ldSeg * 16;
        CP16(dB,          sBh); CP16(dB + 16,          sBh + 16);
        CP16(dB + TILEB,  sBl); CP16(dB + TILEB + 16,  sBl + 16);
    };
    auto stsA = [&](int c, int bf) {
        const int colBase = c * 32 + aCol0;
        uint32_t hw[8], lw[8];
#pragma unroll
        for (int q = 0; q < 4; q++) {
            const float4 v = rA[q];
            const float4 a = *(const float4*)(sA0 + colBase + 4 * q);
            const float4 cc = *(const float4*)(sC0 + colBase + 4 * q);
            float r0 = fmaxf(fmaf(a.x, v.x, cc.x), 0.f);
            float r1 = fmaxf(fmaf(a.y, v.y, cc.y), 0.f);
            float r2 = fmaxf(fmaf(a.z, v.z, cc.z), 0.f);
            float r3 = fmaxf(fmaf(a.w, v.w, cc.w), 0.f);
            pack_split2(r0, r1, hw[2 * q], lw[2 * q]);
            pack_split2(r2, r3, hw[2 * q + 1], lw[2 * q + 1]);
        }
        uint32_t* dH = (uint32_t*)(sm + bf * BUFSZ + ldRow * 80 + (tid & 1) * 32);
        uint32_t* dL = (uint32_t*)(sm + bf * BUFSZ + TILEB + ldRow * 80 + (tid & 1) * 32);
#pragma unroll
        for (int q = 0; q < 8; q++) { dH[q] = hw[q]; dL[q] = lw[q]; }
    };

    ldgA(0);
    cpB(0, 0);
    CP_COMMIT();
    __syncthreads();   // sA0/sC0 ready

    int buf = 0;
    for (int c = 0; c < NCH; c++) {
        stsA(c, buf);
        if (c + 1 < NCH) { cpB(c + 1, buf ^ 1); CP_COMMIT(); ldgA(c + 1); CP_WAIT1(); }
        else             { CP_WAIT0(); }
        __syncthreads();
        const uint32_t aHb = sbase + buf * BUFSZ;
#pragma unroll
        for (int ks = 0; ks < 2; ks++) {
            const uint32_t kb = ks * 32;
            uint32_t bh[4][2], bl[4][2];
            {
                uint32_t t4[4];
                ldm4(t4, aHb + 2 * TILEB + bOff + kb);
                bh[0][0] = t4[0]; bh[0][1] = t4[1]; bh[1][0] = t4[2]; bh[1][1] = t4[3];
                ldm4(t4, aHb + 2 * TILEB + bOff + kb + 16 * 80);
                bh[2][0] = t4[0]; bh[2][1] = t4[1]; bh[3][0] = t4[2]; bh[3][1] = t4[3];
                ldm4(t4, aHb + 3 * TILEB + bOff + kb);
                bl[0][0] = t4[0]; bl[0][1] = t4[1]; bl[1][0] = t4[2]; bl[1][1] = t4[3];
                ldm4(t4, aHb + 3 * TILEB + bOff + kb + 16 * 80);
                bl[2][0] = t4[0]; bl[2][1] = t4[1]; bl[3][0] = t4[2]; bl[3][1] = t4[3];
            }
#pragma unroll
            for (int i = 0; i < 4; i++) {
                uint32_t ah[4], al[4];
                ldm4(ah, aHb + aOff + kb + i * 16 * 80);
                ldm4(al, aHb + TILEB + aOff + kb + i * 16 * 80);
#pragma unroll
                for (int j = 0; j < 4; j++) {
                    mma16816(acc[i][j], ah, bh[j]);
                    mma16816(acc[i][j], al, bh[j]);
                    mma16816(acc[i][j], ah, bl[j]);
                }
            }
        }
        __syncthreads();
        buf ^= 1;
    }

    // ------------- epilogue: bias + Y2 store + BN2 partials -------------
    float2 bias2[4];
#pragma unroll
    for (int j = 0; j < 4; j++)
        bias2[j] = *(const float2*)&bias[n0w + 8 * j + 2 * (lane & 3)];
    float sc[8] = {}, qc[8] = {};
#pragma unroll
    for (int i = 0; i < 4; i++) {
#pragma unroll
        for (int s = 0; s < 2; s++) {
            const int rl = m0w + 16 * i + 8 * s + (lane >> 2);
            float* orow = out + (bRow0 + rl) * C2;
#pragma unroll
            for (int j = 0; j < 4; j++) {
                const int col = n0w + 8 * j + 2 * (lane & 3);
                float v0 = acc[i][j][2 * s] + bias2[j].x;
                float v1 = acc[i][j][2 * s + 1] + bias2[j].y;
                sc[2 * j] += v0;     qc[2 * j] = fmaf(v0, v0, qc[2 * j]);
                sc[2 * j + 1] += v1; qc[2 * j + 1] = fmaf(v1, v1, qc[2 * j + 1]);
                *(float2*)(orow + col) = make_float2(v0, v1);
            }
        }
    }
#pragma unroll
    for (int k = 0; k < 8; k++) {
#pragma unroll
        for (int off = 16; off >= 4; off >>= 1) {
            sc[k] += __shfl_down_sync(0xffffffffu, sc[k], off);
            qc[k] += __shfl_down_sync(0xffffffffu, qc[k], off);
        }
    }
    if (lane < 4) {
#pragma unroll
        for (int j = 0; j < 4; j++) {
            const int cl = n0w + 8 * j + 2 * lane;
            sPs[wm * 128 + cl] = sc[2 * j];         sPq[wm * 128 + cl] = qc[2 * j];
            sPs[wm * 128 + cl + 1] = sc[2 * j + 1]; sPq[wm * 128 + cl + 1] = qc[2 * j + 1];
        }
    }
    __syncthreads();
    if (tid < 128) {
        const float S = sPs[tid] + sPs[128 + tid];
        const float Q = sPq[tid] + sPq[128 + tid];
        const int slot = tid * NPART + b * 64 + blockIdx.x;
        ps[slot] = S; pq[slot] = Q;
    }
}

// ===================== 5) BN finalize from partials =========================
__global__ void reduce_fin(const float* __restrict__ ps, const float* __restrict__ pq,
                           const float* __restrict__ gam, const float* __restrict__ bet,
                           float* __restrict__ ga, float* __restrict__ gc) {
    const int c = blockIdx.x, t = threadIdx.x;
    float s = ps[c * NPART + t] + ps[c * NPART + t + 256];
    float q = pq[c * NPART + t] + pq[c * NPART + t + 256];
    __shared__ float ss[256], qq[256];
    ss[t] = s; qq[t] = q;
    __syncthreads();
    for (int st = 128; st > 0; st >>= 1) {
        if (t < st) { ss[t] += ss[t + st]; qq[t] += qq[t + st]; }
        __syncthreads();
    }
    if (t == 0) {
        const float cnt = (float)(BB * NPTS);
        const float mean = ss[0] / cnt;
        const float var = qq[0] / cnt - mean * mean;
        const float a = gam[c] * rsqrtf(var + 1e-5f);
        ga[c] = a; gc[c] = bet[c] - mean * a;
    }
}

// ===================== 6) BN2 + relu + transpose -> out =====================
__global__ void apply2(float* __restrict__ out) {
    __shared__ float t[32][33];
    const int b = blockIdx.z;
    const int n0 = blockIdx.x * 32, o0 = blockIdx.y * 32;
    const int tx = threadIdx.x, ty = threadIdx.y;
    const float a = g_a1[o0 + tx], c = g_c1[o0 + tx];
#pragma unroll
    for (int i = 0; i < 4; i++) {
        const int n = n0 + ty + 8 * i;
        float v = g_Y2[((size_t)b * NPTS + n) * C2 + o0 + tx];
        t[tx][ty + 8 * i] = fmaxf(fmaf(a, v, c), 0.f);
    }
    __syncthreads();
#pragma unroll
    for (int i = 0; i < 4; i++) {
        const int o = o0 + ty + 8 * i;
        out[((size_t)b * C2 + o) * NPTS + n0 + tx] = t[ty + 8 * i][tx];
    }
}

// ===================== launch ===============================================
extern "C" void kernel_launch(void* const* d_in, const int* in_sizes, int n_in,
                              void* d_out, int out_size) {
    const float* xyz1    = (const float*)d_in[0];
    const float* xyz2    = (const float*)d_in[1];
    const float* points1 = (const float*)d_in[2];
    const float* points2 = (const float*)d_in[3];
    const float* W0      = (const float*)d_in[4];
    const float* b0      = (const float*)d_in[5];
    const float* g0      = (const float*)d_in[6];
    const float* be0     = (const float*)d_in[7];
    const float* W1      = (const float*)d_in[8];
    const float* b1      = (const float*)d_in[9];
    const float* g1      = (const float*)d_in[10];
    const float* be1     = (const float*)d_in[11];
    float* out = (float*)d_out;

    __nv_bfloat16 *p1h, *p1l, *p2h, *p2l;
    __nv_bfloat16 *w0ah, *w0al, *w0bh, *w0bl, *w1h, *w1l;
    float *zt, *y1, *y2, *p1s, *p1q, *p2s, *p2q, *a0, *c0, *a1, *c1;
    cudaGetSymbolAddress((void**)&p1h, g_P1h);  cudaGetSymbolAddress((void**)&p1l, g_P1l);
    cudaGetSymbolAddress((void**)&p2h, g_P2h);  cudaGetSymbolAddress((void**)&p2l, g_P2l);
    cudaGetSymbolAddress((void**)&w0ah, g_W0ah); cudaGetSymbolAddress((void**)&w0al, g_W0al);
    cudaGetSymbolAddress((void**)&w0bh, g_W0bh); cudaGetSymbolAddress((void**)&w0bl, g_W0bl);
    cudaGetSymbolAddress((void**)&w1h, g_W1h);   cudaGetSymbolAddress((void**)&w1l, g_W1l);
    cudaGetSymbolAddress((void**)&zt, g_Zt);
    cudaGetSymbolAddress((void**)&y1, g_Y1);     cudaGetSymbolAddress((void**)&y2, g_Y2);
    cudaGetSymbolAddress((void**)&p1s, g_p1s);   cudaGetSymbolAddress((void**)&p1q, g_p1q);
    cudaGetSymbolAddress((void**)&p2s, g_p2s);   cudaGetSymbolAddress((void**)&p2q, g_p2q);
    cudaGetSymbolAddress((void**)&a0, g_a0);     cudaGetSymbolAddress((void**)&c0, g_c0);
    cudaGetSymbolAddress((void**)&a1, g_a1);     cudaGetSymbolAddress((void**)&c1, g_c1);

    const int SMEM = 2 * BUFSZ + 1536 + 1536 + 2048;    // 87040
    cudaFuncSetAttribute(gemm_mma<C1, D2C, 0, SPTS>, cudaFuncAttributeMaxDynamicSharedMemorySize, SMEM);
    cudaFuncSetAttribute(gemm_mma<C1, D1C, 1, NPTS>, cudaFuncAttributeMaxDynamicSharedMemorySize, SMEM);
    cudaFuncSetAttribute(gemm_y2, cudaFuncAttributeMaxDynamicSharedMemorySize, SMEM);

    knn_part<<<dim3(NPTS / 512, BB, SSPLIT), 256>>>(xyz1, xyz2);
    knn_merge<<<BB * NPTS / 256, 256>>>();
    conv_w<<<(C1 * INCH + C2 * C1 + 255) / 256, 256>>>(W0, W1);
    conv_t<D2C, SPTS><<<dim3(SPTS / 32, D2C / 64, BB), dim3(32, 8)>>>(points2, p2h, p2l);
    conv_t<D1C, NPTS><<<dim3(NPTS / 32, D1C / 64, BB), dim3(32, 8)>>>(points1, p1h, p1l);

    gemm_mma<C1, D2C, 0, SPTS><<<dim3(SPTS / 128, BB, 2), 256, SMEM>>>(
        p2h, p2l, w0bh, w0bl, nullptr, zt, nullptr, nullptr);
    gemm_mma<C1, D1C, 1, NPTS><<<dim3(NPTS / 128, BB, 2), 256, SMEM>>>(
        p1h, p1l, w0ah, w0al, b0, y1, p1s, p1q);

    reduce_fin<<<C1, 256>>>(p1s, p1q, g0, be0, a0, c0);

    gemm_y2<<<dim3(NPTS / 128, BB), 256, SMEM>>>(y1, w1h, w1l, b1, y2, p2s, p2q);

    reduce_fin<<<C2, 256>>>(p2s, p2q, g1, be1, a1, c1);
    apply2<<<dim3(NPTS / 32, C2 / 32, BB), dim3(32, 8)>>>(out);
}

// round 15
// speedup vs baseline: 1.0232x; 1.0232x over previous
#include <cuda_runtime.h>
#include <cuda_bf16.h>
#include <cstdint>

#define BB   8
#define NPTS 8192
#define SPTS 2048
#define D1C  128
#define D2C  256
#define INCH 384
#define C1   256
#define C2   128
#define NPART 512
#define SSPLIT 4
#define SCHUNK (SPTS / SSPLIT)   // 512

// ===================== PTX helpers (standard sm_80+ ISA only) ===============
__device__ __forceinline__ uint32_t smem_u32(const void* p) {
    uint32_t a;
    asm("{ .reg .u64 t; cvta.to.shared.u64 t, %1; cvt.u32.u64 %0, t; }" : "=r"(a) : "l"(p));
    return a;
}
#define CP16(dst, src) \
    asm volatile("cp.async.cg.shared.global [%0], [%1], 16;" :: "r"(dst), "l"(src))
#define CP_COMMIT() asm volatile("cp.async.commit_group;" ::: "memory")
#define CP_WAIT0()  asm volatile("cp.async.wait_group 0;" ::: "memory")
#define CP_WAIT1()  asm volatile("cp.async.wait_group 1;" ::: "memory")

__device__ __forceinline__ void ldm4(uint32_t* r, uint32_t addr) {
    asm volatile("ldmatrix.sync.aligned.m8n8.x4.shared.b16 {%0,%1,%2,%3}, [%4];"
                 : "=r"(r[0]), "=r"(r[1]), "=r"(r[2]), "=r"(r[3]) : "r"(addr));
}
__device__ __forceinline__ void mma16816(float* c, const uint32_t* a, const uint32_t* b) {
    asm volatile("mma.sync.aligned.m16n8k16.row.col.f32.bf16.bf16.f32 "
                 "{%0,%1,%2,%3}, {%4,%5,%6,%7}, {%8,%9}, {%0,%1,%2,%3};"
                 : "+f"(c[0]), "+f"(c[1]), "+f"(c[2]), "+f"(c[3])
                 : "r"(a[0]), "r"(a[1]), "r"(a[2]), "r"(a[3]), "r"(b[0]), "r"(b[1]));
}
__device__ __forceinline__ void split_bf16(float x, __nv_bfloat16& h, __nv_bfloat16& l) {
    h = __float2bfloat16_rn(x);
    l = __float2bfloat16_rn(x - __bfloat162float(h));
}
__device__ __forceinline__ void pack_split2(float v0, float v1, uint32_t& hw, uint32_t& lw) {
    __nv_bfloat16 h0, l0, h1, l1;
    split_bf16(v0, h0, l0); split_bf16(v1, h1, l1);
    hw = (uint32_t)__bfloat16_as_ushort(h0) | ((uint32_t)__bfloat16_as_ushort(h1) << 16);
    lw = (uint32_t)__bfloat16_as_ushort(l0) | ((uint32_t)__bfloat16_as_ushort(l1) << 16);
}

// ===================== scratch ==============================================
__device__ int   g_idx[BB * NPTS * 3];
__device__ float g_w[BB * NPTS * 3];
__device__ float g_pd[BB * SSPLIT * 3 * NPTS];   // [b][z][t][n] coalesced
__device__ int   g_pi[BB * SSPLIT * 3 * NPTS];

__device__ __nv_bfloat16 g_W0ah[C1 * D1C], g_W0al[C1 * D1C];
__device__ __nv_bfloat16 g_W0bh[C1 * D2C], g_W0bl[C1 * D2C];
__device__ __nv_bfloat16 g_W1h[C2 * C1],   g_W1l[C2 * C1];
__device__ __nv_bfloat16 g_P1h[BB * NPTS * D1C], g_P1l[BB * NPTS * D1C];
__device__ __nv_bfloat16 g_P2h[BB * SPTS * D2C], g_P2l[BB * SPTS * D2C];

__device__ float g_Zt[BB * SPTS * C1];     // [b][s][o]
__device__ float g_Y1[BB * NPTS * C1];     // [b][n][o] fp32
__device__ float g_Y2[BB * NPTS * C2];     // [b][n][o]
__device__ float g_p1s[C1 * NPART], g_p1q[C1 * NPART];
__device__ float g_p2s[C2 * NPART], g_p2q[C2 * NPART];
__device__ float g_a0[C1], g_c0[C1], g_a1[C2], g_c1[C2];

// ===================== 1a) 3-NN partial scan ================================
__global__ void knn_part(const float* __restrict__ xyz1,
                         const float* __restrict__ xyz2) {
    __shared__ float4 s2[SCHUNK];
    const int b = blockIdx.y, z = blockIdx.z;
    const int tid = threadIdx.x;
    const int s0 = z * SCHUNK;
    for (int s = tid; s < SCHUNK; s += 256) {
        float x = xyz2[(b * 3 + 0) * SPTS + s0 + s];
        float y = xyz2[(b * 3 + 1) * SPTS + s0 + s];
        float zz = xyz2[(b * 3 + 2) * SPTS + s0 + s];
        s2[s] = make_float4(x, y, zz, x * x + y * y + zz * zz);
    }
    __syncthreads();
    const int n = blockIdx.x * 256 + tid;
    const float px = xyz1[(b * 3 + 0) * NPTS + n];
    const float py = xyz1[(b * 3 + 1) * NPTS + n];
    const float pz = xyz1[(b * 3 + 2) * NPTS + n];
    const float n1 = px * px + py * py + pz * pz;
    float d0 = 3.4e38f, d1 = 3.4e38f, d2 = 3.4e38f;
    int   i0 = 0, i1 = 0, i2 = 0;
#pragma unroll 4
    for (int s = 0; s < SCHUNK; s++) {
        float4 q = s2[s];
        float d = n1 + q.w - 2.f * (px * q.x + py * q.y + pz * q.z);
        if (d < d2) {
            if (d < d1) {
                d2 = d1; i2 = i1;
                if (d < d0) { d1 = d0; i1 = i0; d0 = d; i0 = s0 + s; }
                else        { d1 = d;  i1 = s0 + s; }
            } else { d2 = d; i2 = s0 + s; }
        }
    }
    const int base = (b * SSPLIT + z) * 3 * NPTS + n;
    g_pd[base]            = d0; g_pd[base + NPTS]     = d1; g_pd[base + 2 * NPTS] = d2;
    g_pi[base]            = i0; g_pi[base + NPTS]     = i1; g_pi[base + 2 * NPTS] = i2;
}

// ===================== 1b) 3-NN merge + weights =============================
__global__ void knn_merge() {
    const int g = blockIdx.x * 256 + threadIdx.x;    // b*NPTS + n
    const int b = g / NPTS, n = g % NPTS;
    float d0 = 3.4e38f, d1 = 3.4e38f, d2 = 3.4e38f;
    int   i0 = 0, i1 = 0, i2 = 0;
#pragma unroll
    for (int z = 0; z < SSPLIT; z++) {
#pragma unroll
        for (int t = 0; t < 3; t++) {
            const int base = ((b * SSPLIT + z) * 3 + t) * NPTS + n;
            const float d = g_pd[base];
            const int   s = g_pi[base];
            if (d < d2) {
                if (d < d1) {
                    d2 = d1; i2 = i1;
                    if (d < d0) { d1 = d0; i1 = i0; d0 = d; i0 = s; }
                    else        { d1 = d;  i1 = s; }
                } else { d2 = d; i2 = s; }
            }
        }
    }
    const float r0 = 1.f / (d0 + 1e-8f);
    const float r1 = 1.f / (d1 + 1e-8f);
    const float r2 = 1.f / (d2 + 1e-8f);
    const float inv = 1.f / (r0 + r1 + r2);
    g_idx[g * 3 + 0] = i0; g_idx[g * 3 + 1] = i1; g_idx[g * 3 + 2] = i2;
    g_w[g * 3 + 0] = r0 * inv; g_w[g * 3 + 1] = r1 * inv; g_w[g * 3 + 2] = r2 * inv;
}

// ===================== 2) weight split ======================================
__global__ void conv_w(const float* __restrict__ W0, const float* __restrict__ W1) {
    const int idx = blockIdx.x * 256 + threadIdx.x;
    if (idx < C1 * INCH) {
        const int o = idx / INCH, k = idx % INCH;
        __nv_bfloat16 h, l;
        split_bf16(W0[idx], h, l);
        if (k < D1C) { g_W0ah[o * D1C + k] = h; g_W0al[o * D1C + k] = l; }
        else         { g_W0bh[o * D2C + k - D1C] = h; g_W0bl[o * D2C + k - D1C] = l; }
    } else {
        const int j = idx - C1 * INCH;
        if (j < C2 * C1) { __nv_bfloat16 h, l; split_bf16(W1[j], h, l); g_W1h[j] = h; g_W1l[j] = l; }
    }
}

// ===================== 3) activation transpose + split (vectorized) =========
template <int DD, int NTOT>
__global__ void conv_t(const float* __restrict__ in, __nv_bfloat16* __restrict__ oh,
                       __nv_bfloat16* __restrict__ ol) {
    __shared__ float t[64][33];
    const int b = blockIdx.z;
    const int n0 = blockIdx.x * 32, d0 = blockIdx.y * 64;
    const int tx = threadIdx.x, ty = threadIdx.y;
#pragma unroll
    for (int i = 0; i < 8; i++)
        t[ty + 8 * i][tx] = in[((size_t)b * DD + d0 + ty + 8 * i) * NTOT + n0 + tx];
    __syncthreads();
#pragma unroll
    for (int i = 0; i < 4; i++) {
        const int n = n0 + ty + 8 * i;
        const float v0 = t[2 * tx][ty + 8 * i];
        const float v1 = t[2 * tx + 1][ty + 8 * i];
        uint32_t hw, lw;
        pack_split2(v0, v1, hw, lw);
        const size_t off = (((size_t)b * NTOT + n) * DD + d0) / 2 + tx;
        ((uint32_t*)oh)[off] = hw;
        ((uint32_t*)ol)[off] = lw;
    }
}

#define TILEB 10240          // 128 rows * 80 bytes (32 bf16 + 8 pad)
#define BUFSZ (4 * TILEB)

// ===================== 4a) mma.sync GEMM (bf16 pre-split A via cp.async) ====
// MODE 0: plain fp32 store (Zt). MODE 1: +bias +3-NN gather, BN partials.
template <int NOUT, int KIN, int MODE, int NTOT>
__global__ void __launch_bounds__(256, 2) gemm_mma(
    const __nv_bfloat16* __restrict__ Ah, const __nv_bfloat16* __restrict__ Al,
    const __nv_bfloat16* __restrict__ Bh, const __nv_bfloat16* __restrict__ Bl,
    const float* __restrict__ bias, float* __restrict__ out,
    float* __restrict__ ps, float* __restrict__ pq)
{
    constexpr int NCH = KIN / 32;
    extern __shared__ char sm[];
    const uint32_t sbase = smem_u32(sm);
    int*   sIdx = (int*)(sm + 2 * BUFSZ);
    float* sW   = (float*)(sm + 2 * BUFSZ + 1536);
    float* sPs  = (float*)(sm + 2 * BUFSZ + 3072);
    float* sPq  = sPs + 256;

    const int tid  = threadIdx.x;
    const int lane = tid & 31, wid = tid >> 5;
    const int wm = wid >> 2, wn = wid & 3;
    const int m0w = wm * 64, n0w = wn * 32;
    const int b    = blockIdx.y;
    const int mblk = blockIdx.x * 128;
    const int oblk = blockIdx.z * 128;
    const size_t bRow0 = (size_t)b * NTOT + mblk;

    if (MODE == 1 && tid < 128) {
        const int gi = (b * NPTS + mblk + tid) * 3;
#pragma unroll
        for (int t = 0; t < 3; t++) { sIdx[tid * 3 + t] = g_idx[gi + t]; sW[tid * 3 + t] = g_w[gi + t]; }
    }

    const int ldRow = tid >> 1;
    const int ldSeg = (tid & 1) * 2;

    const uint32_t aOff = (uint32_t)(m0w + (lane & 15)) * 80 + (uint32_t)(lane >> 4) * 16;
    const uint32_t bOff = (uint32_t)(n0w + ((lane >> 4) << 3) + (lane & 7)) * 80 +
                          (uint32_t)((lane >> 3) & 1) * 16;

    float acc[4][4][4] = {};

    auto load_chunk = [&](int c, int buf) {
        const int koff = c * 32;
        const uint32_t dA = sbase + buf * BUFSZ + ldRow * 80 + ldSeg * 16;
        const char* sAh = (const char*)(Ah + (bRow0 + ldRow) * KIN + koff) + ldSeg * 16;
        const char* sAl = (const char*)(Al + (bRow0 + ldRow) * KIN + koff) + ldSeg * 16;
        const char* sBh = (const char*)(Bh + (size_t)(oblk + ldRow) * KIN + koff) + ldSeg * 16;
        const char* sBl = (const char*)(Bl + (size_t)(oblk + ldRow) * KIN + koff) + ldSeg * 16;
        CP16(dA,             sAh);      CP16(dA + 16,             sAh + 16);
        CP16(dA + TILEB,     sAl);      CP16(dA + TILEB + 16,     sAl + 16);
        CP16(dA + 2 * TILEB, sBh);      CP16(dA + 2 * TILEB + 16, sBh + 16);
        CP16(dA + 3 * TILEB, sBl);      CP16(dA + 3 * TILEB + 16, sBl + 16);
    };

    load_chunk(0, 0);
    CP_COMMIT();

    int buf = 0;
    for (int c = 0; c < NCH; c++) {
        if (c + 1 < NCH) { load_chunk(c + 1, buf ^ 1); CP_COMMIT(); CP_WAIT1(); }
        else             { CP_WAIT0(); }
        __syncthreads();
        const uint32_t aHb = sbase + buf * BUFSZ;
#pragma unroll
        for (int ks = 0; ks < 2; ks++) {
            const uint32_t kb = ks * 32;
            uint32_t bh[4][2], bl[4][2];
            {
                uint32_t t4[4];
                ldm4(t4, aHb + 2 * TILEB + bOff + kb);
                bh[0][0] = t4[0]; bh[0][1] = t4[1]; bh[1][0] = t4[2]; bh[1][1] = t4[3];
                ldm4(t4, aHb + 2 * TILEB + bOff + kb + 16 * 80);
                bh[2][0] = t4[0]; bh[2][1] = t4[1]; bh[3][0] = t4[2]; bh[3][1] = t4[3];
                ldm4(t4, aHb + 3 * TILEB + bOff + kb);
                bl[0][0] = t4[0]; bl[0][1] = t4[1]; bl[1][0] = t4[2]; bl[1][1] = t4[3];
                ldm4(t4, aHb + 3 * TILEB + bOff + kb + 16 * 80);
                bl[2][0] = t4[0]; bl[2][1] = t4[1]; bl[3][0] = t4[2]; bl[3][1] = t4[3];
            }
#pragma unroll
            for (int i = 0; i < 4; i++) {
                uint32_t ah[4], al[4];
                ldm4(ah, aHb + aOff + kb + i * 16 * 80);
                ldm4(al, aHb + TILEB + aOff + kb + i * 16 * 80);
#pragma unroll
                for (int j = 0; j < 4; j++) {
                    mma16816(acc[i][j], ah, bh[j]);
                    mma16816(acc[i][j], al, bh[j]);
                    mma16816(acc[i][j], ah, bl[j]);
                }
            }
        }
        __syncthreads();
        buf ^= 1;
    }

    // ------------- epilogue -------------
    float2 bias2[4];
    if (MODE >= 1) {
#pragma unroll
        for (int j = 0; j < 4; j++)
            bias2[j] = *(const float2*)&bias[oblk + n0w + 8 * j + 2 * (lane & 3)];
    }
    float sc[8] = {}, qc[8] = {};
#pragma unroll
    for (int i = 0; i < 4; i++) {
#pragma unroll
        for (int s = 0; s < 2; s++) {
            const int rl = m0w + 16 * i + 8 * s + (lane >> 2);
            float* orow = out + (bRow0 + rl) * NOUT;
            const float *z0 = nullptr, *z1 = nullptr, *z2 = nullptr;
            float w0 = 0.f, w1 = 0.f, w2 = 0.f;
            if (MODE == 1) {
                z0 = g_Zt + ((size_t)b * SPTS + sIdx[rl * 3 + 0]) * C1;
                z1 = g_Zt + ((size_t)b * SPTS + sIdx[rl * 3 + 1]) * C1;
                z2 = g_Zt + ((size_t)b * SPTS + sIdx[rl * 3 + 2]) * C1;
                w0 = sW[rl * 3 + 0]; w1 = sW[rl * 3 + 1]; w2 = sW[rl * 3 + 2];
            }
#pragma unroll
            for (int j = 0; j < 4; j++) {
                const int col = oblk + n0w + 8 * j + 2 * (lane & 3);
                float v0 = acc[i][j][2 * s], v1 = acc[i][j][2 * s + 1];
                if (MODE >= 1) { v0 += bias2[j].x; v1 += bias2[j].y; }
                if (MODE == 1) {
                    float2 za = *(const float2*)(z0 + col);
                    float2 zb = *(const float2*)(z1 + col);
                    float2 zc = *(const float2*)(z2 + col);
                    v0 += w0 * za.x + w1 * zb.x + w2 * zc.x;
                    v1 += w0 * za.y + w1 * zb.y + w2 * zc.y;
                    sc[2 * j] += v0;     qc[2 * j] = fmaf(v0, v0, qc[2 * j]);
                    sc[2 * j + 1] += v1; qc[2 * j + 1] = fmaf(v1, v1, qc[2 * j + 1]);
                }
                *(float2*)(orow + col) = make_float2(v0, v1);
            }
        }
    }
    if (MODE == 1) {
#pragma unroll
        for (int k = 0; k < 8; k++) {
#pragma unroll
            for (int off = 16; off >= 4; off >>= 1) {
                sc[k] += __shfl_down_sync(0xffffffffu, sc[k], off);
                qc[k] += __shfl_down_sync(0xffffffffu, qc[k], off);
            }
        }
        if (lane < 4) {
#pragma unroll
            for (int j = 0; j < 4; j++) {
                const int cl = n0w + 8 * j + 2 * lane;
                sPs[wm * 128 + cl] = sc[2 * j];         sPq[wm * 128 + cl] = qc[2 * j];
                sPs[wm * 128 + cl + 1] = sc[2 * j + 1]; sPq[wm * 128 + cl + 1] = qc[2 * j + 1];
            }
        }
        __syncthreads();
        if (tid < 128) {
            const float S = sPs[tid] + sPs[128 + tid];
            const float Q = sPq[tid] + sPq[128 + tid];
            const int slot = (oblk + tid) * NPART + b * 64 + blockIdx.x;
            ps[slot] = S; pq[slot] = Q;
        }
    }
}

// ===================== 4b) layer-2 GEMM: fp32 Y1 staging + BN + relu ========
__global__ void __launch_bounds__(256, 2) gemm_y2(
    const float* __restrict__ Y1, const __nv_bfloat16* __restrict__ Bh,
    const __nv_bfloat16* __restrict__ Bl, const float* __restrict__ bias,
    float* __restrict__ out, float* __restrict__ ps, float* __restrict__ pq)
{
    constexpr int NCH = C1 / 32;       // 8
    extern __shared__ char sm[];
    const uint32_t sbase = smem_u32(sm);
    float* sA0 = (float*)(sm + 2 * BUFSZ);            // [256]
    float* sC0 = sA0 + 256;
    float* sPs = sC0 + 256;                           // [2][128]
    float* sPq = sPs + 256;

    const int tid  = threadIdx.x;
    const int lane = tid & 31, wid = tid >> 5;
    const int wm = wid >> 2, wn = wid & 3;
    const int m0w = wm * 64, n0w = wn * 32;
    const int b    = blockIdx.y;
    const int mblk = blockIdx.x * 128;
    const size_t bRow0 = (size_t)b * NPTS + mblk;

    sA0[tid] = g_a0[tid];
    sC0[tid] = g_c0[tid];

    const int ldRow = tid >> 1;
    const int ldSeg = (tid & 1) * 2;         // for B cp.async (2x16B)
    const int aCol0 = (tid & 1) * 16;        // 16 fp32 per thread for A

    const uint32_t aOff = (uint32_t)(m0w + (lane & 15)) * 80 + (uint32_t)(lane >> 4) * 16;
    const uint32_t bOff = (uint32_t)(n0w + ((lane >> 4) << 3) + (lane & 7)) * 80 +
                          (uint32_t)((lane >> 3) & 1) * 16;

    float acc[4][4][4] = {};
    float4 rA[4];

    auto ldgA = [&](int c) {
        const float* src = Y1 + (bRow0 + ldRow) * C1 + c * 32 + aCol0;
#pragma unroll
        for (int i = 0; i < 4; i++) rA[i] = __ldg((const float4*)(src + 4 * i));
    };
    auto cpB = [&](int c, int bf) {
        const int koff = c * 32;
        const uint32_t dB = sbase + bf * BUFSZ + 2 * TILEB + ldRow * 80 + ldSeg * 16;
        const char* sBh = (const char*)(Bh + (size_t)ldRow * C1 + koff) + ldSeg * 16;
        const char* sBl = (const char*)(Bl + (size_t)ldRow * C1 + koff) + ldSeg * 16;
        CP16(dB,          sBh); CP16(dB + 16,          sBh + 16);
        CP16(dB + TILEB,  sBl); CP16(dB + TILEB + 16,  sBl + 16);
    };
    auto stsA = [&](int c, int bf) {
        const int colBase = c * 32 + aCol0;
        uint32_t hw[8], lw[8];
#pragma unroll
        for (int q = 0; q < 4; q++) {
            const float4 v = rA[q];
            const float4 a = *(const float4*)(sA0 + colBase + 4 * q);
            const float4 cc = *(const float4*)(sC0 + colBase + 4 * q);
            float r0 = fmaxf(fmaf(a.x, v.x, cc.x), 0.f);
            float r1 = fmaxf(fmaf(a.y, v.y, cc.y), 0.f);
            float r2 = fmaxf(fmaf(a.z, v.z, cc.z), 0.f);
            float r3 = fmaxf(fmaf(a.w, v.w, cc.w), 0.f);
            pack_split2(r0, r1, hw[2 * q], lw[2 * q]);
            pack_split2(r2, r3, hw[2 * q + 1], lw[2 * q + 1]);
        }
        uint32_t* dH = (uint32_t*)(sm + bf * BUFSZ + ldRow * 80 + (tid & 1) * 32);
        uint32_t* dL = (uint32_t*)(sm + bf * BUFSZ + TILEB + ldRow * 80 + (tid & 1) * 32);
#pragma unroll
        for (int q = 0; q < 8; q++) { dH[q] = hw[q]; dL[q] = lw[q]; }
    };

    ldgA(0);
    cpB(0, 0);
    CP_COMMIT();
    __syncthreads();   // sA0/sC0 ready

    int buf = 0;
    for (int c = 0; c < NCH; c++) {
        stsA(c, buf);
        if (c + 1 < NCH) { cpB(c + 1, buf ^ 1); CP_COMMIT(); ldgA(c + 1); CP_WAIT1(); }
        else             { CP_WAIT0(); }
        __syncthreads();
        const uint32_t aHb = sbase + buf * BUFSZ;
#pragma unroll
        for (int ks = 0; ks < 2; ks++) {
            const uint32_t kb = ks * 32;
            uint32_t bh[4][2], bl[4][2];
            {
                uint32_t t4[4];
                ldm4(t4, aHb + 2 * TILEB + bOff + kb);
                bh[0][0] = t4[0]; bh[0][1] = t4[1]; bh[1][0] = t4[2]; bh[1][1] = t4[3];
                ldm4(t4, aHb + 2 * TILEB + bOff + kb + 16 * 80);
                bh[2][0] = t4[0]; bh[2][1] = t4[1]; bh[3][0] = t4[2]; bh[3][1] = t4[3];
                ldm4(t4, aHb + 3 * TILEB + bOff + kb);
                bl[0][0] = t4[0]; bl[0][1] = t4[1]; bl[1][0] = t4[2]; bl[1][1] = t4[3];
                ldm4(t4, aHb + 3 * TILEB + bOff + kb + 16 * 80);
                bl[2][0] = t4[0]; bl[2][1] = t4[1]; bl[3][0] = t4[2]; bl[3][1] = t4[3];
            }
#pragma unroll
            for (int i = 0; i < 4; i++) {
                uint32_t ah[4], al[4];
                ldm4(ah, aHb + aOff + kb + i * 16 * 80);
                ldm4(al, aHb + TILEB + aOff + kb + i * 16 * 80);
#pragma unroll
                for (int j = 0; j < 4; j++) {
                    mma16816(acc[i][j], ah, bh[j]);
                    mma16816(acc[i][j], al, bh[j]);
                    mma16816(acc[i][j], ah, bl[j]);
                }
            }
        }
        __syncthreads();
        buf ^= 1;
    }

    // ------------- epilogue: bias + Y2 store + BN2 partials -------------
    float2 bias2[4];
#pragma unroll
    for (int j = 0; j < 4; j++)
        bias2[j] = *(const float2*)&bias[n0w + 8 * j + 2 * (lane & 3)];
    float sc[8] = {}, qc[8] = {};
#pragma unroll
    for (int i = 0; i < 4; i++) {
#pragma unroll
        for (int s = 0; s < 2; s++) {
            const int rl = m0w + 16 * i + 8 * s + (lane >> 2);
            float* orow = out + (bRow0 + rl) * C2;
#pragma unroll
            for (int j = 0; j < 4; j++) {
                const int col = n0w + 8 * j + 2 * (lane & 3);
                float v0 = acc[i][j][2 * s] + bias2[j].x;
                float v1 = acc[i][j][2 * s + 1] + bias2[j].y;
                sc[2 * j] += v0;     qc[2 * j] = fmaf(v0, v0, qc[2 * j]);
                sc[2 * j + 1] += v1; qc[2 * j + 1] = fmaf(v1, v1, qc[2 * j + 1]);
                *(float2*)(orow + col) = make_float2(v0, v1);
            }
        }
    }
#pragma unroll
    for (int k = 0; k < 8; k++) {
#pragma unroll
        for (int off = 16; off >= 4; off >>= 1) {
            sc[k] += __shfl_down_sync(0xffffffffu, sc[k], off);
            qc[k] += __shfl_down_sync(0xffffffffu, qc[k], off);
        }
    }
    if (lane < 4) {
#pragma unroll
        for (int j = 0; j < 4; j++) {
            const int cl = n0w + 8 * j + 2 * lane;
            sPs[wm * 128 + cl] = sc[2 * j];         sPq[wm * 128 + cl] = qc[2 * j];
            sPs[wm * 128 + cl + 1] = sc[2 * j + 1]; sPq[wm * 128 + cl + 1] = qc[2 * j + 1];
        }
    }
    __syncthreads();
    if (tid < 128) {
        const float S = sPs[tid] + sPs[128 + tid];
        const float Q = sPq[tid] + sPq[128 + tid];
        const int slot = tid * NPART + b * 64 + blockIdx.x;
        ps[slot] = S; pq[slot] = Q;
    }
}

// ===================== 5) BN finalize from partials =========================
__global__ void reduce_fin(const float* __restrict__ ps, const float* __restrict__ pq,
                           const float* __restrict__ gam, const float* __restrict__ bet,
                           float* __restrict__ ga, float* __restrict__ gc) {
    const int c = blockIdx.x, t = threadIdx.x;
    float s = ps[c * NPART + t] + ps[c * NPART + t + 256];
    float q = pq[c * NPART + t] + pq[c * NPART + t + 256];
    __shared__ float ss[256], qq[256];
    ss[t] = s; qq[t] = q;
    __syncthreads();
    for (int st = 128; st > 0; st >>= 1) {
        if (t < st) { ss[t] += ss[t + st]; qq[t] += qq[t + st]; }
        __syncthreads();
    }
    if (t == 0) {
        const float cnt = (float)(BB * NPTS);
        const float mean = ss[0] / cnt;
        const float var = qq[0] / cnt - mean * mean;
        const float a = gam[c] * rsqrtf(var + 1e-5f);
        ga[c] = a; gc[c] = bet[c] - mean * a;
    }
}

// ===================== 6) BN2 + relu + transpose -> out =====================
__global__ void apply2(float* __restrict__ out) {
    __shared__ float t[32][33];
    const int b = blockIdx.z;
    const int n0 = blockIdx.x * 32, o0 = blockIdx.y * 32;
    const int tx = threadIdx.x, ty = threadIdx.y;
    const float a = g_a1[o0 + tx], c = g_c1[o0 + tx];
#pragma unroll
    for (int i = 0; i < 4; i++) {
        const int n = n0 + ty + 8 * i;
        float v = g_Y2[((size_t)b * NPTS + n) * C2 + o0 + tx];
        t[tx][ty + 8 * i] = fmaxf(fmaf(a, v, c), 0.f);
    }
    __syncthreads();
#pragma unroll
    for (int i = 0; i < 4; i++) {
        const int o = o0 + ty + 8 * i;
        out[((size_t)b * C2 + o) * NPTS + n0 + tx] = t[ty + 8 * i][tx];
    }
}

// ===================== launch ===============================================
extern "C" void kernel_launch(void* const* d_in, const int* in_sizes, int n_in,
                              void* d_out, int out_size) {
    const float* xyz1    = (const float*)d_in[0];
    const float* xyz2    = (const float*)d_in[1];
    const float* points1 = (const float*)d_in[2];
    const float* points2 = (const float*)d_in[3];
    const float* W0      = (const float*)d_in[4];
    const float* b0      = (const float*)d_in[5];
    const float* g0      = (const float*)d_in[6];
    const float* be0     = (const float*)d_in[7];
    const float* W1      = (const float*)d_in[8];
    const float* b1      = (const float*)d_in[9];
    const float* g1      = (const float*)d_in[10];
    const float* be1     = (const float*)d_in[11];
    float* out = (float*)d_out;

    __nv_bfloat16 *p1h, *p1l, *p2h, *p2l;
    __nv_bfloat16 *w0ah, *w0al, *w0bh, *w0bl, *w1h, *w1l;
    float *zt, *y1, *y2, *p1s, *p1q, *p2s, *p2q, *a0, *c0, *a1, *c1;
    cudaGetSymbolAddress((void**)&p1h, g_P1h);  cudaGetSymbolAddress((void**)&p1l, g_P1l);
    cudaGetSymbolAddress((void**)&p2h, g_P2h);  cudaGetSymbolAddress((void**)&p2l, g_P2l);
    cudaGetSymbolAddress((void**)&w0ah, g_W0ah); cudaGetSymbolAddress((void**)&w0al, g_W0al);
    cudaGetSymbolAddress((void**)&w0bh, g_W0bh); cudaGetSymbolAddress((void**)&w0bl, g_W0bl);
    cudaGetSymbolAddress((void**)&w1h, g_W1h);   cudaGetSymbolAddress((void**)&w1l, g_W1l);
    cudaGetSymbolAddress((void**)&zt, g_Zt);
    cudaGetSymbolAddress((void**)&y1, g_Y1);     cudaGetSymbolAddress((void**)&y2, g_Y2);
    cudaGetSymbolAddress((void**)&p1s, g_p1s);   cudaGetSymbolAddress((void**)&p1q, g_p1q);
    cudaGetSymbolAddress((void**)&p2s, g_p2s);   cudaGetSymbolAddress((void**)&p2q, g_p2q);
    cudaGetSymbolAddress((void**)&a0, g_a0);     cudaGetSymbolAddress((void**)&c0, g_c0);
    cudaGetSymbolAddress((void**)&a1, g_a1);     cudaGetSymbolAddress((void**)&c1, g_c1);

    const int SMEM = 2 * BUFSZ + 1536 + 1536 + 2048;    // 87040
    cudaFuncSetAttribute(gemm_mma<C1, D2C, 0, SPTS>, cudaFuncAttributeMaxDynamicSharedMemorySize, SMEM);
    cudaFuncSetAttribute(gemm_mma<C1, D1C, 1, NPTS>, cudaFuncAttributeMaxDynamicSharedMemorySize, SMEM);
    cudaFuncSetAttribute(gemm_y2, cudaFuncAttributeMaxDynamicSharedMemorySize, SMEM);

    knn_part<<<dim3(NPTS / 256, BB, SSPLIT), 256>>>(xyz1, xyz2);
    knn_merge<<<BB * NPTS / 256, 256>>>();
    conv_w<<<(C1 * INCH + C2 * C1 + 255) / 256, 256>>>(W0, W1);
    conv_t<D2C, SPTS><<<dim3(SPTS / 32, D2C / 64, BB), dim3(32, 8)>>>(points2, p2h, p2l);
    conv_t<D1C, NPTS><<<dim3(NPTS / 32, D1C / 64, BB), dim3(32, 8)>>>(points1, p1h, p1l);

    gemm_mma<C1, D2C, 0, SPTS><<<dim3(SPTS / 128, BB, 2), 256, SMEM>>>(
        p2h, p2l, w0bh, w0bl, nullptr, zt, nullptr, nullptr);
    gemm_mma<C1, D1C, 1, NPTS><<<dim3(NPTS / 128, BB, 2), 256, SMEM>>>(
        p1h, p1l, w0ah, w0al, b0, y1, p1s, p1q);

    reduce_fin<<<C1, 256>>>(p1s, p1q, g0, be0, a0, c0);

    gemm_y2<<<dim3(NPTS / 128, BB), 256, SMEM>>>(y1, w1h, w1l, b1, y2, p2s, p2q);

    reduce_fin<<<C2, 256>>>(p2s, p2q, g1, be1, a1, c1);
    apply2<<<dim3(NPTS / 32, C2 / 32, BB), dim3(32, 8)>>>(out);
}

// round 16
// speedup vs baseline: 1.1258x; 1.1003x over previous
#include <cuda_runtime.h>
#include <cuda_bf16.h>
#include <cstdint>

#define BB   8
#define NPTS 8192
#define SPTS 2048
#define D1C  128
#define D2C  256
#define INCH 384
#define C1   256
#define C2   128
#define NPART 512
#define SSPLIT 4
#define SCHUNK (SPTS / SSPLIT)   // 512

// ===================== PTX helpers (standard sm_80+ ISA only) ===============
__device__ __forceinline__ uint32_t smem_u32(const void* p) {
    uint32_t a;
    asm("{ .reg .u64 t; cvta.to.shared.u64 t, %1; cvt.u32.u64 %0, t; }" : "=r"(a) : "l"(p));
    return a;
}
#define CP16(dst, src) \
    asm volatile("cp.async.cg.shared.global [%0], [%1], 16;" :: "r"(dst), "l"(src))
#define CP_COMMIT() asm volatile("cp.async.commit_group;" ::: "memory")
#define CP_WAIT0()  asm volatile("cp.async.wait_group 0;" ::: "memory")
#define CP_WAIT1()  asm volatile("cp.async.wait_group 1;" ::: "memory")

__device__ __forceinline__ void ldm4(uint32_t* r, uint32_t addr) {
    asm volatile("ldmatrix.sync.aligned.m8n8.x4.shared.b16 {%0,%1,%2,%3}, [%4];"
                 : "=r"(r[0]), "=r"(r[1]), "=r"(r[2]), "=r"(r[3]) : "r"(addr));
}
__device__ __forceinline__ void mma16816(float* c, const uint32_t* a, const uint32_t* b) {
    asm volatile("mma.sync.aligned.m16n8k16.row.col.f32.bf16.bf16.f32 "
                 "{%0,%1,%2,%3}, {%4,%5,%6,%7}, {%8,%9}, {%0,%1,%2,%3};"
                 : "+f"(c[0]), "+f"(c[1]), "+f"(c[2]), "+f"(c[3])
                 : "r"(a[0]), "r"(a[1]), "r"(a[2]), "r"(a[3]), "r"(b[0]), "r"(b[1]));
}
__device__ __forceinline__ void split_bf16(float x, __nv_bfloat16& h, __nv_bfloat16& l) {
    h = __float2bfloat16_rn(x);
    l = __float2bfloat16_rn(x - __bfloat162float(h));
}
__device__ __forceinline__ void pack_split2(float v0, float v1, uint32_t& hw, uint32_t& lw) {
    __nv_bfloat16 h0, l0, h1, l1;
    split_bf16(v0, h0, l0); split_bf16(v1, h1, l1);
    hw = (uint32_t)__bfloat16_as_ushort(h0) | ((uint32_t)__bfloat16_as_ushort(h1) << 16);
    lw = (uint32_t)__bfloat16_as_ushort(l0) | ((uint32_t)__bfloat16_as_ushort(l1) << 16);
}

// ===================== scratch ==============================================
__device__ int   g_idx[BB * NPTS * 3];
__device__ float g_w[BB * NPTS * 3];
__device__ float g_pd[BB * SSPLIT * 3 * NPTS];   // [b][z][t][n] coalesced
__device__ int   g_pi[BB * SSPLIT * 3 * NPTS];

__device__ __nv_bfloat16 g_W0ah[C1 * D1C], g_W0al[C1 * D1C];
__device__ __nv_bfloat16 g_W0bh[C1 * D2C], g_W0bl[C1 * D2C];
__device__ __nv_bfloat16 g_W1h[C2 * C1],   g_W1l[C2 * C1];
__device__ __nv_bfloat16 g_P1h[BB * NPTS * D1C], g_P1l[BB * NPTS * D1C];
__device__ __nv_bfloat16 g_P2h[BB * SPTS * D2C], g_P2l[BB * SPTS * D2C];

__device__ float g_Zt[BB * SPTS * C1];     // [b][s][o]
__device__ float g_Y1[BB * NPTS * C1];     // [b][n][o] fp32
__device__ float g_Y2[BB * NPTS * C2];     // [b][n][o]
__device__ float g_p1s[C1 * NPART], g_p1q[C1 * NPART];
__device__ float g_p2s[C2 * NPART], g_p2q[C2 * NPART];
__device__ float g_a0[C1], g_c0[C1], g_a1[C2], g_c1[C2];

// ===================== 1a) 3-NN partial scan ================================
__global__ void knn_part(const float* __restrict__ xyz1,
                         const float* __restrict__ xyz2) {
    __shared__ float4 s2[SCHUNK];
    const int b = blockIdx.y, z = blockIdx.z;
    const int tid = threadIdx.x;
    const int s0 = z * SCHUNK;
    for (int s = tid; s < SCHUNK; s += 256) {
        float x = xyz2[(b * 3 + 0) * SPTS + s0 + s];
        float y = xyz2[(b * 3 + 1) * SPTS + s0 + s];
        float zz = xyz2[(b * 3 + 2) * SPTS + s0 + s];
        s2[s] = make_float4(x, y, zz, x * x + y * y + zz * zz);
    }
    __syncthreads();
    const int n = blockIdx.x * 256 + tid;
    const float px = xyz1[(b * 3 + 0) * NPTS + n];
    const float py = xyz1[(b * 3 + 1) * NPTS + n];
    const float pz = xyz1[(b * 3 + 2) * NPTS + n];
    const float n1 = px * px + py * py + pz * pz;
    float d0 = 3.4e38f, d1 = 3.4e38f, d2 = 3.4e38f;
    int   i0 = 0, i1 = 0, i2 = 0;
#pragma unroll 4
    for (int s = 0; s < SCHUNK; s++) {
        float4 q = s2[s];
        float d = n1 + q.w - 2.f * (px * q.x + py * q.y + pz * q.z);
        if (d < d2) {
            if (d < d1) {
                d2 = d1; i2 = i1;
                if (d < d0) { d1 = d0; i1 = i0; d0 = d; i0 = s0 + s; }
                else        { d1 = d;  i1 = s0 + s; }
            } else { d2 = d; i2 = s0 + s; }
        }
    }
    const int base = (b * SSPLIT + z) * 3 * NPTS + n;
    g_pd[base]            = d0; g_pd[base + NPTS]     = d1; g_pd[base + 2 * NPTS] = d2;
    g_pi[base]            = i0; g_pi[base + NPTS]     = i1; g_pi[base + 2 * NPTS] = i2;
}

// ===================== 1b) 3-NN merge + weights =============================
__global__ void knn_merge() {
    const int g = blockIdx.x * 256 + threadIdx.x;    // b*NPTS + n
    const int b = g / NPTS, n = g % NPTS;
    float d0 = 3.4e38f, d1 = 3.4e38f, d2 = 3.4e38f;
    int   i0 = 0, i1 = 0, i2 = 0;
#pragma unroll
    for (int z = 0; z < SSPLIT; z++) {
#pragma unroll
        for (int t = 0; t < 3; t++) {
            const int base = ((b * SSPLIT + z) * 3 + t) * NPTS + n;
            const float d = g_pd[base];
            const int   s = g_pi[base];
            if (d < d2) {
                if (d < d1) {
                    d2 = d1; i2 = i1;
                    if (d < d0) { d1 = d0; i1 = i0; d0 = d; i0 = s; }
                    else        { d1 = d;  i1 = s; }
                } else { d2 = d; i2 = s; }
            }
        }
    }
    const float r0 = 1.f / (d0 + 1e-8f);
    const float r1 = 1.f / (d1 + 1e-8f);
    const float r2 = 1.f / (d2 + 1e-8f);
    const float inv = 1.f / (r0 + r1 + r2);
    g_idx[g * 3 + 0] = i0; g_idx[g * 3 + 1] = i1; g_idx[g * 3 + 2] = i2;
    g_w[g * 3 + 0] = r0 * inv; g_w[g * 3 + 1] = r1 * inv; g_w[g * 3 + 2] = r2 * inv;
}

// ===================== 2) weight split ======================================
__global__ void conv_w(const float* __restrict__ W0, const float* __restrict__ W1) {
    const int idx = blockIdx.x * 256 + threadIdx.x;
    if (idx < C1 * INCH) {
        const int o = idx / INCH, k = idx % INCH;
        __nv_bfloat16 h, l;
        split_bf16(W0[idx], h, l);
        if (k < D1C) { g_W0ah[o * D1C + k] = h; g_W0al[o * D1C + k] = l; }
        else         { g_W0bh[o * D2C + k - D1C] = h; g_W0bl[o * D2C + k - D1C] = l; }
    } else {
        const int j = idx - C1 * INCH;
        if (j < C2 * C1) { __nv_bfloat16 h, l; split_bf16(W1[j], h, l); g_W1h[j] = h; g_W1l[j] = l; }
    }
}

// ===================== 3) activation transpose + split (vectorized) =========
template <int DD, int NTOT>
__global__ void conv_t(const float* __restrict__ in, __nv_bfloat16* __restrict__ oh,
                       __nv_bfloat16* __restrict__ ol) {
    __shared__ float t[64][33];
    const int b = blockIdx.z;
    const int n0 = blockIdx.x * 32, d0 = blockIdx.y * 64;
    const int tx = threadIdx.x, ty = threadIdx.y;
#pragma unroll
    for (int i = 0; i < 8; i++)
        t[ty + 8 * i][tx] = in[((size_t)b * DD + d0 + ty + 8 * i) * NTOT + n0 + tx];
    __syncthreads();
#pragma unroll
    for (int i = 0; i < 4; i++) {
        const int n = n0 + ty + 8 * i;
        const float v0 = t[2 * tx][ty + 8 * i];
        const float v1 = t[2 * tx + 1][ty + 8 * i];
        uint32_t hw, lw;
        pack_split2(v0, v1, hw, lw);
        const size_t off = (((size_t)b * NTOT + n) * DD + d0) / 2 + tx;
        ((uint32_t*)oh)[off] = hw;
        ((uint32_t*)ol)[off] = lw;
    }
}

#define TILEB 10240          // 128 rows * 80 bytes (32 bf16 + 8 pad)
#define BUFSZ (4 * TILEB)

// ===================== 4a) mma.sync GEMM (bf16 pre-split A via cp.async) ====
// MODE 0: plain fp32 store (Zt). MODE 1: +bias +3-NN gather, BN partials.
template <int NOUT, int KIN, int MODE, int NTOT>
__global__ void __launch_bounds__(256, 2) gemm_mma(
    const __nv_bfloat16* __restrict__ Ah, const __nv_bfloat16* __restrict__ Al,
    const __nv_bfloat16* __restrict__ Bh, const __nv_bfloat16* __restrict__ Bl,
    const float* __restrict__ bias, float* __restrict__ out,
    float* __restrict__ ps, float* __restrict__ pq)
{
    constexpr int NCH = KIN / 32;
    extern __shared__ char sm[];
    const uint32_t sbase = smem_u32(sm);
    int*   sIdx = (int*)(sm + 2 * BUFSZ);
    float* sW   = (float*)(sm + 2 * BUFSZ + 1536);
    float* sPs  = (float*)(sm + 2 * BUFSZ + 3072);
    float* sPq  = sPs + 256;

    const int tid  = threadIdx.x;
    const int lane = tid & 31, wid = tid >> 5;
    const int wm = wid >> 2, wn = wid & 3;
    const int m0w = wm * 64, n0w = wn * 32;
    const int b    = blockIdx.y;
    const int mblk = blockIdx.x * 128;
    const int oblk = blockIdx.z * 128;
    const size_t bRow0 = (size_t)b * NTOT + mblk;

    if (MODE == 1 && tid < 128) {
        const int gi = (b * NPTS + mblk + tid) * 3;
#pragma unroll
        for (int t = 0; t < 3; t++) { sIdx[tid * 3 + t] = g_idx[gi + t]; sW[tid * 3 + t] = g_w[gi + t]; }
    }

    const int ldRow = tid >> 1;
    const int ldSeg = (tid & 1) * 2;

    const uint32_t aOff = (uint32_t)(m0w + (lane & 15)) * 80 + (uint32_t)(lane >> 4) * 16;
    const uint32_t bOff = (uint32_t)(n0w + ((lane >> 4) << 3) + (lane & 7)) * 80 +
                          (uint32_t)((lane >> 3) & 1) * 16;

    float acc[4][4][4] = {};

    auto load_chunk = [&](int c, int buf) {
        const int koff = c * 32;
        const uint32_t dA = sbase + buf * BUFSZ + ldRow * 80 + ldSeg * 16;
        const char* sAh = (const char*)(Ah + (bRow0 + ldRow) * KIN + koff) + ldSeg * 16;
        const char* sAl = (const char*)(Al + (bRow0 + ldRow) * KIN + koff) + ldSeg * 16;
        const char* sBh = (const char*)(Bh + (size_t)(oblk + ldRow) * KIN + koff) + ldSeg * 16;
        const char* sBl = (const char*)(Bl + (size_t)(oblk + ldRow) * KIN + koff) + ldSeg * 16;
        CP16(dA,             sAh);      CP16(dA + 16,             sAh + 16);
        CP16(dA + TILEB,     sAl);      CP16(dA + TILEB + 16,     sAl + 16);
        CP16(dA + 2 * TILEB, sBh);      CP16(dA + 2 * TILEB + 16, sBh + 16);
        CP16(dA + 3 * TILEB, sBl);      CP16(dA + 3 * TILEB + 16, sBl + 16);
    };

    load_chunk(0, 0);
    CP_COMMIT();

    int buf = 0;
    for (int c = 0; c < NCH; c++) {
        if (c + 1 < NCH) { load_chunk(c + 1, buf ^ 1); CP_COMMIT(); CP_WAIT1(); }
        else             { CP_WAIT0(); }
        __syncthreads();
        const uint32_t aHb = sbase + buf * BUFSZ;
#pragma unroll
        for (int ks = 0; ks < 2; ks++) {
            const uint32_t kb = ks * 32;
            uint32_t bh[4][2], bl[4][2];
            {
                uint32_t t4[4];
                ldm4(t4, aHb + 2 * TILEB + bOff + kb);
                bh[0][0] = t4[0]; bh[0][1] = t4[1]; bh[1][0] = t4[2]; bh[1][1] = t4[3];
                ldm4(t4, aHb + 2 * TILEB + bOff + kb + 16 * 80);
                bh[2][0] = t4[0]; bh[2][1] = t4[1]; bh[3][0] = t4[2]; bh[3][1] = t4[3];
                ldm4(t4, aHb + 3 * TILEB + bOff + kb);
                bl[0][0] = t4[0]; bl[0][1] = t4[1]; bl[1][0] = t4[2]; bl[1][1] = t4[3];
                ldm4(t4, aHb + 3 * TILEB + bOff + kb + 16 * 80);
                bl[2][0] = t4[0]; bl[2][1] = t4[1]; bl[3][0] = t4[2]; bl[3][1] = t4[3];
            }
#pragma unroll
            for (int i = 0; i < 4; i++) {
                uint32_t ah[4], al[4];
                ldm4(ah, aHb + aOff + kb + i * 16 * 80);
                ldm4(al, aHb + TILEB + aOff + kb + i * 16 * 80);
#pragma unroll
                for (int j = 0; j < 4; j++) {
                    mma16816(acc[i][j], ah, bh[j]);
                    mma16816(acc[i][j], al, bh[j]);
                    mma16816(acc[i][j], ah, bl[j]);
                }
            }
        }
        __syncthreads();
        buf ^= 1;
    }

    // ------------- epilogue -------------
    float2 bias2[4];
    if (MODE >= 1) {
#pragma unroll
        for (int j = 0; j < 4; j++)
            bias2[j] = *(const float2*)&bias[oblk + n0w + 8 * j + 2 * (lane & 3)];
    }
    float sc[8] = {}, qc[8] = {};
#pragma unroll
    for (int i = 0; i < 4; i++) {
#pragma unroll
        for (int s = 0; s < 2; s++) {
            const int rl = m0w + 16 * i + 8 * s + (lane >> 2);
            float* orow = out + (bRow0 + rl) * NOUT;
            const float *z0 = nullptr, *z1 = nullptr, *z2 = nullptr;
            float w0 = 0.f, w1 = 0.f, w2 = 0.f;
            if (MODE == 1) {
                z0 = g_Zt + ((size_t)b * SPTS + sIdx[rl * 3 + 0]) * C1;
                z1 = g_Zt + ((size_t)b * SPTS + sIdx[rl * 3 + 1]) * C1;
                z2 = g_Zt + ((size_t)b * SPTS + sIdx[rl * 3 + 2]) * C1;
                w0 = sW[rl * 3 + 0]; w1 = sW[rl * 3 + 1]; w2 = sW[rl * 3 + 2];
            }
#pragma unroll
            for (int j = 0; j < 4; j++) {
                const int col = oblk + n0w + 8 * j + 2 * (lane & 3);
                float v0 = acc[i][j][2 * s], v1 = acc[i][j][2 * s + 1];
                if (MODE >= 1) { v0 += bias2[j].x; v1 += bias2[j].y; }
                if (MODE == 1) {
                    float2 za = *(const float2*)(z0 + col);
                    float2 zb = *(const float2*)(z1 + col);
                    float2 zc = *(const float2*)(z2 + col);
                    v0 += w0 * za.x + w1 * zb.x + w2 * zc.x;
                    v1 += w0 * za.y + w1 * zb.y + w2 * zc.y;
                    sc[2 * j] += v0;     qc[2 * j] = fmaf(v0, v0, qc[2 * j]);
                    sc[2 * j + 1] += v1; qc[2 * j + 1] = fmaf(v1, v1, qc[2 * j + 1]);
                }
                *(float2*)(orow + col) = make_float2(v0, v1);
            }
        }
    }
    if (MODE == 1) {
#pragma unroll
        for (int k = 0; k < 8; k++) {
#pragma unroll
            for (int off = 16; off >= 4; off >>= 1) {
                sc[k] += __shfl_down_sync(0xffffffffu, sc[k], off);
                qc[k] += __shfl_down_sync(0xffffffffu, qc[k], off);
            }
        }
        if (lane < 4) {
#pragma unroll
            for (int j = 0; j < 4; j++) {
                const int cl = n0w + 8 * j + 2 * lane;
                sPs[wm * 128 + cl] = sc[2 * j];         sPq[wm * 128 + cl] = qc[2 * j];
                sPs[wm * 128 + cl + 1] = sc[2 * j + 1]; sPq[wm * 128 + cl + 1] = qc[2 * j + 1];
            }
        }
        __syncthreads();
        if (tid < 128) {
            const float S = sPs[tid] + sPs[128 + tid];
            const float Q = sPq[tid] + sPq[128 + tid];
            const int slot = (oblk + tid) * NPART + b * 64 + blockIdx.x;
            ps[slot] = S; pq[slot] = Q;
        }
    }
}

// ===================== 4b) layer-2 GEMM: fp32 Y1 staging + BN + relu ========
__global__ void __launch_bounds__(256, 2) gemm_y2(
    const float* __restrict__ Y1, const __nv_bfloat16* __restrict__ Bh,
    const __nv_bfloat16* __restrict__ Bl, const float* __restrict__ bias,
    float* __restrict__ out, float* __restrict__ ps, float* __restrict__ pq)
{
    constexpr int NCH = C1 / 32;       // 8
    extern __shared__ char sm[];
    const uint32_t sbase = smem_u32(sm);
    float* sA0 = (float*)(sm + 2 * BUFSZ);            // [256]
    float* sC0 = sA0 + 256;
    float* sPs = sC0 + 256;                           // [2][128]
    float* sPq = sPs + 256;

    const int tid  = threadIdx.x;
    const int lane = tid & 31, wid = tid >> 5;
    const int wm = wid >> 2, wn = wid & 3;
    const int m0w = wm * 64, n0w = wn * 32;
    const int b    = blockIdx.y;
    const int mblk = blockIdx.x * 128;
    const size_t bRow0 = (size_t)b * NPTS + mblk;

    sA0[tid] = g_a0[tid];
    sC0[tid] = g_c0[tid];

    const int ldRow = tid >> 1;
    const int ldSeg = (tid & 1) * 2;         // for B cp.async (2x16B)
    const int aCol0 = (tid & 1) * 16;        // 16 fp32 per thread for A

    const uint32_t aOff = (uint32_t)(m0w + (lane & 15)) * 80 + (uint32_t)(lane >> 4) * 16;
    const uint32_t bOff = (uint32_t)(n0w + ((lane >> 4) << 3) + (lane & 7)) * 80 +
                          (uint32_t)((lane >> 3) & 1) * 16;

    float acc[4][4][4] = {};
    float4 rA[4];

    auto ldgA = [&](int c) {
        const float* src = Y1 + (bRow0 + ldRow) * C1 + c * 32 + aCol0;
#pragma unroll
        for (int i = 0; i < 4; i++) rA[i] = __ldg((const float4*)(src + 4 * i));
    };
    auto cpB = [&](int c, int bf) {
        const int koff = c * 32;
        const uint32_t dB = sbase + bf * BUFSZ + 2 * TILEB + ldRow * 80 + ldSeg * 16;
        const char* sBh = (const char*)(Bh + (size_t)ldRow * C1 + koff) + ldSeg * 16;
        const char* sBl = (const char*)(Bl + (size_t)ldRow * C1 + koff) + ldSeg * 16;
        CP16(dB,          sBh); CP16(dB + 16,          sBh + 16);
        CP16(dB + TILEB,  sBl); CP16(dB + TILEB + 16,  sBl + 16);
    };
    auto stsA = [&](int c, int bf) {
        const int colBase = c * 32 + aCol0;
        uint32_t hw[8], lw[8];
#pragma unroll
        for (int q = 0; q < 4; q++) {
            const float4 v = rA[q];
            const float4 a = *(const float4*)(sA0 + colBase + 4 * q);
            const float4 cc = *(const float4*)(sC0 + colBase + 4 * q);
            float r0 = fmaxf(fmaf(a.x, v.x, cc.x), 0.f);
            float r1 = fmaxf(fmaf(a.y, v.y, cc.y), 0.f);
            float r2 = fmaxf(fmaf(a.z, v.z, cc.z), 0.f);
            float r3 = fmaxf(fmaf(a.w, v.w, cc.w), 0.f);
            pack_split2(r0, r1, hw[2 * q], lw[2 * q]);
            pack_split2(r2, r3, hw[2 * q + 1], lw[2 * q + 1]);
        }
        uint32_t* dH = (uint32_t*)(sm + bf * BUFSZ + ldRow * 80 + (tid & 1) * 32);
        uint32_t* dL = (uint32_t*)(sm + bf * BUFSZ + TILEB + ldRow * 80 + (tid & 1) * 32);
#pragma unroll
        for (int q = 0; q < 8; q++) { dH[q] = hw[q]; dL[q] = lw[q]; }
    };

    ldgA(0);
    cpB(0, 0);
    CP_COMMIT();
    __syncthreads();   // sA0/sC0 ready

    int buf = 0;
    for (int c = 0; c < NCH; c++) {
        stsA(c, buf);
        if (c + 1 < NCH) { cpB(c + 1, buf ^ 1); CP_COMMIT(); ldgA(c + 1); CP_WAIT1(); }
        else             { CP_WAIT0(); }
        __syncthreads();
        const uint32_t aHb = sbase + buf * BUFSZ;
#pragma unroll
        for (int ks = 0; ks < 2; ks++) {
            const uint32_t kb = ks * 32;
            uint32_t bh[4][2], bl[4][2];
            {
                uint32_t t4[4];
                ldm4(t4, aHb + 2 * TILEB + bOff + kb);
                bh[0][0] = t4[0]; bh[0][1] = t4[1]; bh[1][0] = t4[2]; bh[1][1] = t4[3];
                ldm4(t4, aHb + 2 * TILEB + bOff + kb + 16 * 80);
                bh[2][0] = t4[0]; bh[2][1] = t4[1]; bh[3][0] = t4[2]; bh[3][1] = t4[3];
                ldm4(t4, aHb + 3 * TILEB + bOff + kb);
                bl[0][0] = t4[0]; bl[0][1] = t4[1]; bl[1][0] = t4[2]; bl[1][1] = t4[3];
                ldm4(t4, aHb + 3 * TILEB + bOff + kb + 16 * 80);
                bl[2][0] = t4[0]; bl[2][1] = t4[1]; bl[3][0] = t4[2]; bl[3][1] = t4[3];
            }
#pragma unroll
            for (int i = 0; i < 4; i++) {
                uint32_t ah[4], al[4];
                ldm4(ah, aHb + aOff + kb + i * 16 * 80);
                ldm4(al, aHb + TILEB + aOff + kb + i * 16 * 80);
#pragma unroll
                for (int j = 0; j < 4; j++) {
                    mma16816(acc[i][j], ah, bh[j]);
                    mma16816(acc[i][j], al, bh[j]);
                    mma16816(acc[i][j], ah, bl[j]);
                }
            }
        }
        __syncthreads();
        buf ^= 1;
    }

    // ------------- epilogue: bias + Y2 store + BN2 partials -------------
    float2 bias2[4];
#pragma unroll
    for (int j = 0; j < 4; j++)
        bias2[j] = *(const float2*)&bias[n0w + 8 * j + 2 * (lane & 3)];
    float sc[8] = {}, qc[8] = {};
#pragma unroll
    for (int i = 0; i < 4; i++) {
#pragma unroll
        for (int s = 0; s < 2; s++) {
            const int rl = m0w + 16 * i + 8 * s + (lane >> 2);
            float* orow = out + (bRow0 + rl) * C2;
#pragma unroll
            for (int j = 0; j < 4; j++) {
                const int col = n0w + 8 * j + 2 * (lane & 3);
                float v0 = acc[i][j][2 * s] + bias2[j].x;
                float v1 = acc[i][j][2 * s + 1] + bias2[j].y;
                sc[2 * j] += v0;     qc[2 * j] = fmaf(v0, v0, qc[2 * j]);
                sc[2 * j + 1] += v1; qc[2 * j + 1] = fmaf(v1, v1, qc[2 * j + 1]);
                *(float2*)(orow + col) = make_float2(v0, v1);
            }
        }
    }
#pragma unroll
    for (int k = 0; k < 8; k++) {
#pragma unroll
        for (int off = 16; off >= 4; off >>= 1) {
            sc[k] += __shfl_down_sync(0xffffffffu, sc[k], off);
            qc[k] += __shfl_down_sync(0xffffffffu, qc[k], off);
        }
    }
    if (lane < 4) {
#pragma unroll
        for (int j = 0; j < 4; j++) {
            const int cl = n0w + 8 * j + 2 * lane;
            sPs[wm * 128 + cl] = sc[2 * j];         sPq[wm * 128 + cl] = qc[2 * j];
            sPs[wm * 128 + cl + 1] = sc[2 * j + 1]; sPq[wm * 128 + cl + 1] = qc[2 * j + 1];
        }
    }
    __syncthreads();
    if (tid < 128) {
        const float S = sPs[tid] + sPs[128 + tid];
        const float Q = sPq[tid] + sPq[128 + tid];
        const int slot = tid * NPART + b * 64 + blockIdx.x;
        ps[slot] = S; pq[slot] = Q;
    }
}

// ===================== 5) BN finalize from partials =========================
__global__ void reduce_fin(const float* __restrict__ ps, const float* __restrict__ pq,
                           const float* __restrict__ gam, const float* __restrict__ bet,
                           float* __restrict__ ga, float* __restrict__ gc) {
    const int c = blockIdx.x, t = threadIdx.x;
    float s = ps[c * NPART + t] + ps[c * NPART + t + 256];
    float q = pq[c * NPART + t] + pq[c * NPART + t + 256];
    __shared__ float ss[256], qq[256];
    ss[t] = s; qq[t] = q;
    __syncthreads();
    for (int st = 128; st > 0; st >>= 1) {
        if (t < st) { ss[t] += ss[t + st]; qq[t] += qq[t + st]; }
        __syncthreads();
    }
    if (t == 0) {
        const float cnt = (float)(BB * NPTS);
        const float mean = ss[0] / cnt;
        const float var = qq[0] / cnt - mean * mean;
        const float a = gam[c] * rsqrtf(var + 1e-5f);
        ga[c] = a; gc[c] = bet[c] - mean * a;
    }
}

// ===================== 6) BN2 + relu + transpose -> out =====================
__global__ void apply2(float* __restrict__ out) {
    __shared__ float t[32][33];
    const int b = blockIdx.z;
    const int n0 = blockIdx.x * 32, o0 = blockIdx.y * 32;
    const int tx = threadIdx.x, ty = threadIdx.y;
    const float a = g_a1[o0 + tx], c = g_c1[o0 + tx];
#pragma unroll
    for (int i = 0; i < 4; i++) {
        const int n = n0 + ty + 8 * i;
        float v = g_Y2[((size_t)b * NPTS + n) * C2 + o0 + tx];
        t[tx][ty + 8 * i] = fmaxf(fmaf(a, v, c), 0.f);
    }
    __syncthreads();
#pragma unroll
    for (int i = 0; i < 4; i++) {
        const int o = o0 + ty + 8 * i;
        out[((size_t)b * C2 + o) * NPTS + n0 + tx] = t[ty + 8 * i][tx];
    }
}

// ===================== launch ===============================================
extern "C" void kernel_launch(void* const* d_in, const int* in_sizes, int n_in,
                              void* d_out, int out_size) {
    const float* xyz1    = (const float*)d_in[0];
    const float* xyz2    = (const float*)d_in[1];
    const float* points1 = (const float*)d_in[2];
    const float* points2 = (const float*)d_in[3];
    const float* W0      = (const float*)d_in[4];
    const float* b0      = (const float*)d_in[5];
    const float* g0      = (const float*)d_in[6];
    const float* be0     = (const float*)d_in[7];
    const float* W1      = (const float*)d_in[8];
    const float* b1      = (const float*)d_in[9];
    const float* g1      = (const float*)d_in[10];
    const float* be1     = (const float*)d_in[11];
    float* out = (float*)d_out;

    __nv_bfloat16 *p1h, *p1l, *p2h, *p2l;
    __nv_bfloat16 *w0ah, *w0al, *w0bh, *w0bl, *w1h, *w1l;
    float *zt, *y1, *y2, *p1s, *p1q, *p2s, *p2q, *a0, *c0, *a1, *c1;
    cudaGetSymbolAddress((void**)&p1h, g_P1h);  cudaGetSymbolAddress((void**)&p1l, g_P1l);
    cudaGetSymbolAddress((void**)&p2h, g_P2h);  cudaGetSymbolAddress((void**)&p2l, g_P2l);
    cudaGetSymbolAddress((void**)&w0ah, g_W0ah); cudaGetSymbolAddress((void**)&w0al, g_W0al);
    cudaGetSymbolAddress((void**)&w0bh, g_W0bh); cudaGetSymbolAddress((void**)&w0bl, g_W0bl);
    cudaGetSymbolAddress((void**)&w1h, g_W1h);   cudaGetSymbolAddress((void**)&w1l, g_W1l);
    cudaGetSymbolAddress((void**)&zt, g_Zt);
    cudaGetSymbolAddress((void**)&y1, g_Y1);     cudaGetSymbolAddress((void**)&y2, g_Y2);
    cudaGetSymbolAddress((void**)&p1s, g_p1s);   cudaGetSymbolAddress((void**)&p1q, g_p1q);
    cudaGetSymbolAddress((void**)&p2s, g_p2s);   cudaGetSymbolAddress((void**)&p2q, g_p2q);
    cudaGetSymbolAddress((void**)&a0, g_a0);     cudaGetSymbolAddress((void**)&c0, g_c0);
    cudaGetSymbolAddress((void**)&a1, g_a1);     cudaGetSymbolAddress((void**)&c1, g_c1);

    const int SMEM = 2 * BUFSZ + 1536 + 1536 + 2048;    // 87040
    cudaFuncSetAttribute(gemm_mma<C1, D2C, 0, SPTS>, cudaFuncAttributeMaxDynamicSharedMemorySize, SMEM);
    cudaFuncSetAttribute(gemm_mma<C1, D1C, 1, NPTS>, cudaFuncAttributeMaxDynamicSharedMemorySize, SMEM);
    cudaFuncSetAttribute(gemm_y2, cudaFuncAttributeMaxDynamicSharedMemorySize, SMEM);

    // lazy-init side stream + events (first call is the non-captured
    // correctness run, so creation happens outside graph capture; reused
    // identically on every subsequent call -> deterministic work)
    static cudaStream_t s_knn = nullptr;
    static cudaEvent_t  ev_fork = nullptr, ev_knn = nullptr;
    if (s_knn == nullptr) {
        cudaStreamCreateWithFlags(&s_knn, cudaStreamNonBlocking);
        cudaEventCreateWithFlags(&ev_fork, cudaEventDisableTiming);
        cudaEventCreateWithFlags(&ev_knn, cudaEventDisableTiming);
    }

    // fork: knn chain on s_knn, conv/zt chain on default stream
    cudaEventRecord(ev_fork, 0);
    cudaStreamWaitEvent(s_knn, ev_fork, 0);
    knn_part<<<dim3(NPTS / 256, BB, SSPLIT), 256, 0, s_knn>>>(xyz1, xyz2);
    knn_merge<<<BB * NPTS / 256, 256, 0, s_knn>>>();
    cudaEventRecord(ev_knn, s_knn);

    conv_w<<<(C1 * INCH + C2 * C1 + 255) / 256, 256>>>(W0, W1);
    conv_t<D2C, SPTS><<<dim3(SPTS / 32, D2C / 64, BB), dim3(32, 8)>>>(points2, p2h, p2l);
    conv_t<D1C, NPTS><<<dim3(NPTS / 32, D1C / 64, BB), dim3(32, 8)>>>(points1, p1h, p1l);

    gemm_mma<C1, D2C, 0, SPTS><<<dim3(SPTS / 128, BB, 2), 256, SMEM>>>(
        p2h, p2l, w0bh, w0bl, nullptr, zt, nullptr, nullptr);

    // join: gemm_y1 consumes g_idx/g_w from the knn chain
    cudaStreamWaitEvent(0, ev_knn, 0);
    gemm_mma<C1, D1C, 1, NPTS><<<dim3(NPTS / 128, BB, 2), 256, SMEM>>>(
        p1h, p1l, w0ah, w0al, b0, y1, p1s, p1q);

    reduce_fin<<<C1, 256>>>(p1s, p1q, g0, be0, a0, c0);

    gemm_y2<<<dim3(NPTS / 128, BB), 256, SMEM>>>(y1, w1h, w1l, b1, y2, p2s, p2q);

    reduce_fin<<<C2, 256>>>(p2s, p2q, g1, be1, a1, c1);
    apply2<<<dim3(NPTS / 32, C2 / 32, BB), dim3(32, 8)>>>(out);
}

// round 17
// speedup vs baseline: 1.1269x; 1.0010x over previous
#include <cuda_runtime.h>
#include <cuda_bf16.h>
#include <cstdint>

#define BB   8
#define NPTS 8192
#define SPTS 2048
#define D1C  128
#define D2C  256
#define INCH 384
#define C1   256
#define C2   128
#define NPART 512
#define SSPLIT 4
#define SCHUNK (SPTS / SSPLIT)   // 512

// ===================== PTX helpers (standard sm_80+ ISA only) ===============
__device__ __forceinline__ uint32_t smem_u32(const void* p) {
    uint32_t a;
    asm("{ .reg .u64 t; cvta.to.shared.u64 t, %1; cvt.u32.u64 %0, t; }" : "=r"(a) : "l"(p));
    return a;
}
#define CP16(dst, src) \
    asm volatile("cp.async.cg.shared.global [%0], [%1], 16;" :: "r"(dst), "l"(src))
#define CP_COMMIT() asm volatile("cp.async.commit_group;" ::: "memory")
#define CP_WAIT0()  asm volatile("cp.async.wait_group 0;" ::: "memory")
#define CP_WAIT1()  asm volatile("cp.async.wait_group 1;" ::: "memory")

__device__ __forceinline__ void ldm4(uint32_t* r, uint32_t addr) {
    asm volatile("ldmatrix.sync.aligned.m8n8.x4.shared.b16 {%0,%1,%2,%3}, [%4];"
                 : "=r"(r[0]), "=r"(r[1]), "=r"(r[2]), "=r"(r[3]) : "r"(addr));
}
__device__ __forceinline__ void mma16816(float* c, const uint32_t* a, const uint32_t* b) {
    asm volatile("mma.sync.aligned.m16n8k16.row.col.f32.bf16.bf16.f32 "
                 "{%0,%1,%2,%3}, {%4,%5,%6,%7}, {%8,%9}, {%0,%1,%2,%3};"
                 : "+f"(c[0]), "+f"(c[1]), "+f"(c[2]), "+f"(c[3])
                 : "r"(a[0]), "r"(a[1]), "r"(a[2]), "r"(a[3]), "r"(b[0]), "r"(b[1]));
}
__device__ __forceinline__ void split_bf16(float x, __nv_bfloat16& h, __nv_bfloat16& l) {
    h = __float2bfloat16_rn(x);
    l = __float2bfloat16_rn(x - __bfloat162float(h));
}
__device__ __forceinline__ void pack_split2(float v0, float v1, uint32_t& hw, uint32_t& lw) {
    __nv_bfloat16 h0, l0, h1, l1;
    split_bf16(v0, h0, l0); split_bf16(v1, h1, l1);
    hw = (uint32_t)__bfloat16_as_ushort(h0) | ((uint32_t)__bfloat16_as_ushort(h1) << 16);
    lw = (uint32_t)__bfloat16_as_ushort(l0) | ((uint32_t)__bfloat16_as_ushort(l1) << 16);
}

// ===================== scratch ==============================================
__device__ int   g_idx[BB * NPTS * 3];
__device__ float g_w[BB * NPTS * 3];
__device__ float g_pd[BB * SSPLIT * 3 * NPTS];   // [b][z][t][n] coalesced
__device__ int   g_pi[BB * SSPLIT * 3 * NPTS];

__device__ __nv_bfloat16 g_W0ah[C1 * D1C], g_W0al[C1 * D1C];
__device__ __nv_bfloat16 g_W0bh[C1 * D2C], g_W0bl[C1 * D2C];
__device__ __nv_bfloat16 g_W1h[C2 * C1],   g_W1l[C2 * C1];
__device__ __nv_bfloat16 g_P1h[BB * NPTS * D1C], g_P1l[BB * NPTS * D1C];
__device__ __nv_bfloat16 g_P2h[BB * SPTS * D2C], g_P2l[BB * SPTS * D2C];

__device__ float g_Zt[BB * SPTS * C1];     // [b][s][o]
__device__ float g_Y1[BB * NPTS * C1];     // [b][n][o] fp32
__device__ float g_Y2[BB * NPTS * C2];     // [b][n][o]
__device__ float g_p1s[C1 * NPART], g_p1q[C1 * NPART];
__device__ float g_p2s[C2 * NPART], g_p2q[C2 * NPART];
__device__ float g_a0[C1], g_c0[C1], g_a1[C2], g_c1[C2];

// ===================== 1a) 3-NN partial scan ================================
__global__ void knn_part(const float* __restrict__ xyz1,
                         const float* __restrict__ xyz2) {
    __shared__ float4 s2[SCHUNK];
    const int b = blockIdx.y, z = blockIdx.z;
    const int tid = threadIdx.x;
    const int s0 = z * SCHUNK;
    for (int s = tid; s < SCHUNK; s += 256) {
        float x = xyz2[(b * 3 + 0) * SPTS + s0 + s];
        float y = xyz2[(b * 3 + 1) * SPTS + s0 + s];
        float zz = xyz2[(b * 3 + 2) * SPTS + s0 + s];
        s2[s] = make_float4(x, y, zz, x * x + y * y + zz * zz);
    }
    __syncthreads();
    const int n = blockIdx.x * 256 + tid;
    const float px = xyz1[(b * 3 + 0) * NPTS + n];
    const float py = xyz1[(b * 3 + 1) * NPTS + n];
    const float pz = xyz1[(b * 3 + 2) * NPTS + n];
    const float n1 = px * px + py * py + pz * pz;
    float d0 = 3.4e38f, d1 = 3.4e38f, d2 = 3.4e38f;
    int   i0 = 0, i1 = 0, i2 = 0;
#pragma unroll 4
    for (int s = 0; s < SCHUNK; s++) {
        float4 q = s2[s];
        float d = n1 + q.w - 2.f * (px * q.x + py * q.y + pz * q.z);
        if (d < d2) {
            if (d < d1) {
                d2 = d1; i2 = i1;
                if (d < d0) { d1 = d0; i1 = i0; d0 = d; i0 = s0 + s; }
                else        { d1 = d;  i1 = s0 + s; }
            } else { d2 = d; i2 = s0 + s; }
        }
    }
    const int base = (b * SSPLIT + z) * 3 * NPTS + n;
    g_pd[base]            = d0; g_pd[base + NPTS]     = d1; g_pd[base + 2 * NPTS] = d2;
    g_pi[base]            = i0; g_pi[base + NPTS]     = i1; g_pi[base + 2 * NPTS] = i2;
}

// ===================== 1b) 3-NN merge + weights =============================
__global__ void knn_merge() {
    const int g = blockIdx.x * 256 + threadIdx.x;    // b*NPTS + n
    const int b = g / NPTS, n = g % NPTS;
    float d0 = 3.4e38f, d1 = 3.4e38f, d2 = 3.4e38f;
    int   i0 = 0, i1 = 0, i2 = 0;
#pragma unroll
    for (int z = 0; z < SSPLIT; z++) {
#pragma unroll
        for (int t = 0; t < 3; t++) {
            const int base = ((b * SSPLIT + z) * 3 + t) * NPTS + n;
            const float d = g_pd[base];
            const int   s = g_pi[base];
            if (d < d2) {
                if (d < d1) {
                    d2 = d1; i2 = i1;
                    if (d < d0) { d1 = d0; i1 = i0; d0 = d; i0 = s; }
                    else        { d1 = d;  i1 = s; }
                } else { d2 = d; i2 = s; }
            }
        }
    }
    const float r0 = 1.f / (d0 + 1e-8f);
    const float r1 = 1.f / (d1 + 1e-8f);
    const float r2 = 1.f / (d2 + 1e-8f);
    const float inv = 1.f / (r0 + r1 + r2);
    g_idx[g * 3 + 0] = i0; g_idx[g * 3 + 1] = i1; g_idx[g * 3 + 2] = i2;
    g_w[g * 3 + 0] = r0 * inv; g_w[g * 3 + 1] = r1 * inv; g_w[g * 3 + 2] = r2 * inv;
}

// ===================== 2) weight split ======================================
__global__ void conv_w(const float* __restrict__ W0, const float* __restrict__ W1) {
    const int idx = blockIdx.x * 256 + threadIdx.x;
    if (idx < C1 * INCH) {
        const int o = idx / INCH, k = idx % INCH;
        __nv_bfloat16 h, l;
        split_bf16(W0[idx], h, l);
        if (k < D1C) { g_W0ah[o * D1C + k] = h; g_W0al[o * D1C + k] = l; }
        else         { g_W0bh[o * D2C + k - D1C] = h; g_W0bl[o * D2C + k - D1C] = l; }
    } else {
        const int j = idx - C1 * INCH;
        if (j < C2 * C1) { __nv_bfloat16 h, l; split_bf16(W1[j], h, l); g_W1h[j] = h; g_W1l[j] = l; }
    }
}

// ===================== 3) activation transpose + split (vectorized) =========
template <int DD, int NTOT>
__global__ void conv_t(const float* __restrict__ in, __nv_bfloat16* __restrict__ oh,
                       __nv_bfloat16* __restrict__ ol) {
    __shared__ float t[64][33];
    const int b = blockIdx.z;
    const int n0 = blockIdx.x * 32, d0 = blockIdx.y * 64;
    const int tx = threadIdx.x, ty = threadIdx.y;
#pragma unroll
    for (int i = 0; i < 8; i++)
        t[ty + 8 * i][tx] = in[((size_t)b * DD + d0 + ty + 8 * i) * NTOT + n0 + tx];
    __syncthreads();
#pragma unroll
    for (int i = 0; i < 4; i++) {
        const int n = n0 + ty + 8 * i;
        const float v0 = t[2 * tx][ty + 8 * i];
        const float v1 = t[2 * tx + 1][ty + 8 * i];
        uint32_t hw, lw;
        pack_split2(v0, v1, hw, lw);
        const size_t off = (((size_t)b * NTOT + n) * DD + d0) / 2 + tx;
        ((uint32_t*)oh)[off] = hw;
        ((uint32_t*)ol)[off] = lw;
    }
}

#define TILEB 10240          // 128 rows * 80 bytes (32 bf16 + 8 pad)
#define BUFSZ (4 * TILEB)

// ===================== 4a) mma.sync GEMM (bf16 pre-split A via cp.async) ====
// MODE 0: plain fp32 store (Zt). MODE 1: +bias +3-NN gather, BN partials.
template <int NOUT, int KIN, int MODE, int NTOT>
__global__ void __launch_bounds__(256, 2) gemm_mma(
    const __nv_bfloat16* __restrict__ Ah, const __nv_bfloat16* __restrict__ Al,
    const __nv_bfloat16* __restrict__ Bh, const __nv_bfloat16* __restrict__ Bl,
    const float* __restrict__ bias, float* __restrict__ out,
    float* __restrict__ ps, float* __restrict__ pq)
{
    constexpr int NCH = KIN / 32;
    extern __shared__ char sm[];
    const uint32_t sbase = smem_u32(sm);
    int*   sIdx = (int*)(sm + 2 * BUFSZ);
    float* sW   = (float*)(sm + 2 * BUFSZ + 1536);
    float* sPs  = (float*)(sm + 2 * BUFSZ + 3072);
    float* sPq  = sPs + 256;

    const int tid  = threadIdx.x;
    const int lane = tid & 31, wid = tid >> 5;
    const int wm = wid >> 2, wn = wid & 3;
    const int m0w = wm * 64, n0w = wn * 32;
    const int b    = blockIdx.y;
    const int mblk = blockIdx.x * 128;
    const int oblk = blockIdx.z * 128;
    const size_t bRow0 = (size_t)b * NTOT + mblk;

    if (MODE == 1 && tid < 128) {
        const int gi = (b * NPTS + mblk + tid) * 3;
#pragma unroll
        for (int t = 0; t < 3; t++) { sIdx[tid * 3 + t] = g_idx[gi + t]; sW[tid * 3 + t] = g_w[gi + t]; }
    }

    const int ldRow = tid >> 1;
    const int ldSeg = (tid & 1) * 2;

    const uint32_t aOff = (uint32_t)(m0w + (lane & 15)) * 80 + (uint32_t)(lane >> 4) * 16;
    const uint32_t bOff = (uint32_t)(n0w + ((lane >> 4) << 3) + (lane & 7)) * 80 +
                          (uint32_t)((lane >> 3) & 1) * 16;

    float acc[4][4][4] = {};

    auto load_chunk = [&](int c, int buf) {
        const int koff = c * 32;
        const uint32_t dA = sbase + buf * BUFSZ + ldRow * 80 + ldSeg * 16;
        const char* sAh = (const char*)(Ah + (bRow0 + ldRow) * KIN + koff) + ldSeg * 16;
        const char* sAl = (const char*)(Al + (bRow0 + ldRow) * KIN + koff) + ldSeg * 16;
        const char* sBh = (const char*)(Bh + (size_t)(oblk + ldRow) * KIN + koff) + ldSeg * 16;
        const char* sBl = (const char*)(Bl + (size_t)(oblk + ldRow) * KIN + koff) + ldSeg * 16;
        CP16(dA,             sAh);      CP16(dA + 16,             sAh + 16);
        CP16(dA + TILEB,     sAl);      CP16(dA + TILEB + 16,     sAl + 16);
        CP16(dA + 2 * TILEB, sBh);      CP16(dA + 2 * TILEB + 16, sBh + 16);
        CP16(dA + 3 * TILEB, sBl);      CP16(dA + 3 * TILEB + 16, sBl + 16);
    };

    load_chunk(0, 0);
    CP_COMMIT();

    int buf = 0;
    for (int c = 0; c < NCH; c++) {
        if (c + 1 < NCH) { load_chunk(c + 1, buf ^ 1); CP_COMMIT(); CP_WAIT1(); }
        else             { CP_WAIT0(); }
        __syncthreads();
        const uint32_t aHb = sbase + buf * BUFSZ;
#pragma unroll
        for (int ks = 0; ks < 2; ks++) {
            const uint32_t kb = ks * 32;
            uint32_t bh[4][2], bl[4][2];
            {
                uint32_t t4[4];
                ldm4(t4, aHb + 2 * TILEB + bOff + kb);
                bh[0][0] = t4[0]; bh[0][1] = t4[1]; bh[1][0] = t4[2]; bh[1][1] = t4[3];
                ldm4(t4, aHb + 2 * TILEB + bOff + kb + 16 * 80);
                bh[2][0] = t4[0]; bh[2][1] = t4[1]; bh[3][0] = t4[2]; bh[3][1] = t4[3];
                ldm4(t4, aHb + 3 * TILEB + bOff + kb);
                bl[0][0] = t4[0]; bl[0][1] = t4[1]; bl[1][0] = t4[2]; bl[1][1] = t4[3];
                ldm4(t4, aHb + 3 * TILEB + bOff + kb + 16 * 80);
                bl[2][0] = t4[0]; bl[2][1] = t4[1]; bl[3][0] = t4[2]; bl[3][1] = t4[3];
            }
#pragma unroll
            for (int i = 0; i < 4; i++) {
                uint32_t ah[4], al[4];
                ldm4(ah, aHb + aOff + kb + i * 16 * 80);
                ldm4(al, aHb + TILEB + aOff + kb + i * 16 * 80);
#pragma unroll
                for (int j = 0; j < 4; j++) {
                    mma16816(acc[i][j], ah, bh[j]);
                    mma16816(acc[i][j], al, bh[j]);
                    mma16816(acc[i][j], ah, bl[j]);
                }
            }
        }
        __syncthreads();
        buf ^= 1;
    }

    // ------------- epilogue -------------
    float2 bias2[4];
    if (MODE >= 1) {
#pragma unroll
        for (int j = 0; j < 4; j++)
            bias2[j] = *(const float2*)&bias[oblk + n0w + 8 * j + 2 * (lane & 3)];
    }
    float sc[8] = {}, qc[8] = {};
#pragma unroll
    for (int i = 0; i < 4; i++) {
#pragma unroll
        for (int s = 0; s < 2; s++) {
            const int rl = m0w + 16 * i + 8 * s + (lane >> 2);
            float* orow = out + (bRow0 + rl) * NOUT;
            const float *z0 = nullptr, *z1 = nullptr, *z2 = nullptr;
            float w0 = 0.f, w1 = 0.f, w2 = 0.f;
            if (MODE == 1) {
                z0 = g_Zt + ((size_t)b * SPTS + sIdx[rl * 3 + 0]) * C1;
                z1 = g_Zt + ((size_t)b * SPTS + sIdx[rl * 3 + 1]) * C1;
                z2 = g_Zt + ((size_t)b * SPTS + sIdx[rl * 3 + 2]) * C1;
                w0 = sW[rl * 3 + 0]; w1 = sW[rl * 3 + 1]; w2 = sW[rl * 3 + 2];
            }
#pragma unroll
            for (int j = 0; j < 4; j++) {
                const int col = oblk + n0w + 8 * j + 2 * (lane & 3);
                float v0 = acc[i][j][2 * s], v1 = acc[i][j][2 * s + 1];
                if (MODE >= 1) { v0 += bias2[j].x; v1 += bias2[j].y; }
                if (MODE == 1) {
                    float2 za = *(const float2*)(z0 + col);
                    float2 zb = *(const float2*)(z1 + col);
                    float2 zc = *(const float2*)(z2 + col);
                    v0 += w0 * za.x + w1 * zb.x + w2 * zc.x;
                    v1 += w0 * za.y + w1 * zb.y + w2 * zc.y;
                    sc[2 * j] += v0;     qc[2 * j] = fmaf(v0, v0, qc[2 * j]);
                    sc[2 * j + 1] += v1; qc[2 * j + 1] = fmaf(v1, v1, qc[2 * j + 1]);
                }
                *(float2*)(orow + col) = make_float2(v0, v1);
            }
        }
    }
    if (MODE == 1) {
#pragma unroll
        for (int k = 0; k < 8; k++) {
#pragma unroll
            for (int off = 16; off >= 4; off >>= 1) {
                sc[k] += __shfl_down_sync(0xffffffffu, sc[k], off);
                qc[k] += __shfl_down_sync(0xffffffffu, qc[k], off);
            }
        }
        if (lane < 4) {
#pragma unroll
            for (int j = 0; j < 4; j++) {
                const int cl = n0w + 8 * j + 2 * lane;
                sPs[wm * 128 + cl] = sc[2 * j];         sPq[wm * 128 + cl] = qc[2 * j];
                sPs[wm * 128 + cl + 1] = sc[2 * j + 1]; sPq[wm * 128 + cl + 1] = qc[2 * j + 1];
            }
        }
        __syncthreads();
        if (tid < 128) {
            const float S = sPs[tid] + sPs[128 + tid];
            const float Q = sPq[tid] + sPq[128 + tid];
            const int slot = (oblk + tid) * NPART + b * 64 + blockIdx.x;
            ps[slot] = S; pq[slot] = Q;
        }
    }
}

// ===================== 4b) layer-2 GEMM: fp32 Y1 staging + BN + relu ========
__global__ void __launch_bounds__(256, 2) gemm_y2(
    const float* __restrict__ Y1, const __nv_bfloat16* __restrict__ Bh,
    const __nv_bfloat16* __restrict__ Bl, const float* __restrict__ bias,
    float* __restrict__ out, float* __restrict__ ps, float* __restrict__ pq)
{
    constexpr int NCH = C1 / 32;       // 8
    extern __shared__ char sm[];
    const uint32_t sbase = smem_u32(sm);
    float* sA0 = (float*)(sm + 2 * BUFSZ);            // [256]
    float* sC0 = sA0 + 256;
    float* sPs = sC0 + 256;                           // [2][128]
    float* sPq = sPs + 256;

    const int tid  = threadIdx.x;
    const int lane = tid & 31, wid = tid >> 5;
    const int wm = wid >> 2, wn = wid & 3;
    const int m0w = wm * 64, n0w = wn * 32;
    const int b    = blockIdx.y;
    const int mblk = blockIdx.x * 128;
    const size_t bRow0 = (size_t)b * NPTS + mblk;

    sA0[tid] = g_a0[tid];
    sC0[tid] = g_c0[tid];

    const int ldRow = tid >> 1;
    const int ldSeg = (tid & 1) * 2;         // for B cp.async (2x16B)
    const int aCol0 = (tid & 1) * 16;        // 16 fp32 per thread for A

    const uint32_t aOff = (uint32_t)(m0w + (lane & 15)) * 80 + (uint32_t)(lane >> 4) * 16;
    const uint32_t bOff = (uint32_t)(n0w + ((lane >> 4) << 3) + (lane & 7)) * 80 +
                          (uint32_t)((lane >> 3) & 1) * 16;

    float acc[4][4][4] = {};
    float4 rA[4];

    auto ldgA = [&](int c) {
        const float* src = Y1 + (bRow0 + ldRow) * C1 + c * 32 + aCol0;
#pragma unroll
        for (int i = 0; i < 4; i++) rA[i] = __ldg((const float4*)(src + 4 * i));
    };
    auto cpB = [&](int c, int bf) {
        const int koff = c * 32;
        const uint32_t dB = sbase + bf * BUFSZ + 2 * TILEB + ldRow * 80 + ldSeg * 16;
        const char* sBh = (const char*)(Bh + (size_t)ldRow * C1 + koff) + ldSeg * 16;
        const char* sBl = (const char*)(Bl + (size_t)ldRow * C1 + koff) + ldSeg * 16;
        CP16(dB,          sBh); CP16(dB + 16,          sBh + 16);
        CP16(dB + TILEB,  sBl); CP16(dB + TILEB + 16,  sBl + 16);
    };
    auto stsA = [&](int c, int bf) {
        const int colBase = c * 32 + aCol0;
        uint32_t hw[8], lw[8];
#pragma unroll
        for (int q = 0; q < 4; q++) {
            const float4 v = rA[q];
            const float4 a = *(const float4*)(sA0 + colBase + 4 * q);
            const float4 cc = *(const float4*)(sC0 + colBase + 4 * q);
            float r0 = fmaxf(fmaf(a.x, v.x, cc.x), 0.f);
            float r1 = fmaxf(fmaf(a.y, v.y, cc.y), 0.f);
            float r2 = fmaxf(fmaf(a.z, v.z, cc.z), 0.f);
            float r3 = fmaxf(fmaf(a.w, v.w, cc.w), 0.f);
            pack_split2(r0, r1, hw[2 * q], lw[2 * q]);
            pack_split2(r2, r3, hw[2 * q + 1], lw[2 * q + 1]);
        }
        uint32_t* dH = (uint32_t*)(sm + bf * BUFSZ + ldRow * 80 + (tid & 1) * 32);
        uint32_t* dL = (uint32_t*)(sm + bf * BUFSZ + TILEB + ldRow * 80 + (tid & 1) * 32);
#pragma unroll
        for (int q = 0; q < 8; q++) { dH[q] = hw[q]; dL[q] = lw[q]; }
    };

    ldgA(0);
    cpB(0, 0);
    CP_COMMIT();
    __syncthreads();   // sA0/sC0 ready

    int buf = 0;
    for (int c = 0; c < NCH; c++) {
        stsA(c, buf);
        if (c + 1 < NCH) { cpB(c + 1, buf ^ 1); CP_COMMIT(); ldgA(c + 1); CP_WAIT1(); }
        else             { CP_WAIT0(); }
        __syncthreads();
        const uint32_t aHb = sbase + buf * BUFSZ;
#pragma unroll
        for (int ks = 0; ks < 2; ks++) {
            const uint32_t kb = ks * 32;
            uint32_t bh[4][2], bl[4][2];
            {
                uint32_t t4[4];
                ldm4(t4, aHb + 2 * TILEB + bOff + kb);
                bh[0][0] = t4[0]; bh[0][1] = t4[1]; bh[1][0] = t4[2]; bh[1][1] = t4[3];
                ldm4(t4, aHb + 2 * TILEB + bOff + kb + 16 * 80);
                bh[2][0] = t4[0]; bh[2][1] = t4[1]; bh[3][0] = t4[2]; bh[3][1] = t4[3];
                ldm4(t4, aHb + 3 * TILEB + bOff + kb);
                bl[0][0] = t4[0]; bl[0][1] = t4[1]; bl[1][0] = t4[2]; bl[1][1] = t4[3];
                ldm4(t4, aHb + 3 * TILEB + bOff + kb + 16 * 80);
                bl[2][0] = t4[0]; bl[2][1] = t4[1]; bl[3][0] = t4[2]; bl[3][1] = t4[3];
            }
#pragma unroll
            for (int i = 0; i < 4; i++) {
                uint32_t ah[4], al[4];
                ldm4(ah, aHb + aOff + kb + i * 16 * 80);
                ldm4(al, aHb + TILEB + aOff + kb + i * 16 * 80);
#pragma unroll
                for (int j = 0; j < 4; j++) {
                    mma16816(acc[i][j], ah, bh[j]);
                    mma16816(acc[i][j], al, bh[j]);
                    mma16816(acc[i][j], ah, bl[j]);
                }
            }
        }
        __syncthreads();
        buf ^= 1;
    }

    // ------------- epilogue: bias + Y2 store + BN2 partials -------------
    float2 bias2[4];
#pragma unroll
    for (int j = 0; j < 4; j++)
        bias2[j] = *(const float2*)&bias[n0w + 8 * j + 2 * (lane & 3)];
    float sc[8] = {}, qc[8] = {};
#pragma unroll
    for (int i = 0; i < 4; i++) {
#pragma unroll
        for (int s = 0; s < 2; s++) {
            const int rl = m0w + 16 * i + 8 * s + (lane >> 2);
            float* orow = out + (bRow0 + rl) * C2;
#pragma unroll
            for (int j = 0; j < 4; j++) {
                const int col = n0w + 8 * j + 2 * (lane & 3);
                float v0 = acc[i][j][2 * s] + bias2[j].x;
                float v1 = acc[i][j][2 * s + 1] + bias2[j].y;
                sc[2 * j] += v0;     qc[2 * j] = fmaf(v0, v0, qc[2 * j]);
                sc[2 * j + 1] += v1; qc[2 * j + 1] = fmaf(v1, v1, qc[2 * j + 1]);
                *(float2*)(orow + col) = make_float2(v0, v1);
            }
        }
    }
#pragma unroll
    for (int k = 0; k < 8; k++) {
#pragma unroll
        for (int off = 16; off >= 4; off >>= 1) {
            sc[k] += __shfl_down_sync(0xffffffffu, sc[k], off);
            qc[k] += __shfl_down_sync(0xffffffffu, qc[k], off);
        }
    }
    if (lane < 4) {
#pragma unroll
        for (int j = 0; j < 4; j++) {
            const int cl = n0w + 8 * j + 2 * lane;
            sPs[wm * 128 + cl] = sc[2 * j];         sPq[wm * 128 + cl] = qc[2 * j];
            sPs[wm * 128 + cl + 1] = sc[2 * j + 1]; sPq[wm * 128 + cl + 1] = qc[2 * j + 1];
        }
    }
    __syncthreads();
    if (tid < 128) {
        const float S = sPs[tid] + sPs[128 + tid];
        const float Q = sPq[tid] + sPq[128 + tid];
        const int slot = tid * NPART + b * 64 + blockIdx.x;
        ps[slot] = S; pq[slot] = Q;
    }
}

// ===================== 5) BN finalize from partials =========================
__global__ void reduce_fin(const float* __restrict__ ps, const float* __restrict__ pq,
                           const float* __restrict__ gam, const float* __restrict__ bet,
                           float* __restrict__ ga, float* __restrict__ gc) {
    const int c = blockIdx.x, t = threadIdx.x;
    float s = ps[c * NPART + t] + ps[c * NPART + t + 256];
    float q = pq[c * NPART + t] + pq[c * NPART + t + 256];
    __shared__ float ss[256], qq[256];
    ss[t] = s; qq[t] = q;
    __syncthreads();
    for (int st = 128; st > 0; st >>= 1) {
        if (t < st) { ss[t] += ss[t + st]; qq[t] += qq[t + st]; }
        __syncthreads();
    }
    if (t == 0) {
        const float cnt = (float)(BB * NPTS);
        const float mean = ss[0] / cnt;
        const float var = qq[0] / cnt - mean * mean;
        const float a = gam[c] * rsqrtf(var + 1e-5f);
        ga[c] = a; gc[c] = bet[c] - mean * a;
    }
}

// ===================== 6) BN2 + relu + transpose -> out =====================
__global__ void apply2(float* __restrict__ out) {
    __shared__ float t[32][33];
    const int b = blockIdx.z;
    const int n0 = blockIdx.x * 32, o0 = blockIdx.y * 32;
    const int tx = threadIdx.x, ty = threadIdx.y;
    const float a = g_a1[o0 + tx], c = g_c1[o0 + tx];
#pragma unroll
    for (int i = 0; i < 4; i++) {
        const int n = n0 + ty + 8 * i;
        float v = g_Y2[((size_t)b * NPTS + n) * C2 + o0 + tx];
        t[tx][ty + 8 * i] = fmaxf(fmaf(a, v, c), 0.f);
    }
    __syncthreads();
#pragma unroll
    for (int i = 0; i < 4; i++) {
        const int o = o0 + ty + 8 * i;
        out[((size_t)b * C2 + o) * NPTS + n0 + tx] = t[ty + 8 * i][tx];
    }
}

// ===================== launch ===============================================
extern "C" void kernel_launch(void* const* d_in, const int* in_sizes, int n_in,
                              void* d_out, int out_size) {
    const float* xyz1    = (const float*)d_in[0];
    const float* xyz2    = (const float*)d_in[1];
    const float* points1 = (const float*)d_in[2];
    const float* points2 = (const float*)d_in[3];
    const float* W0      = (const float*)d_in[4];
    const float* b0      = (const float*)d_in[5];
    const float* g0      = (const float*)d_in[6];
    const float* be0     = (const float*)d_in[7];
    const float* W1      = (const float*)d_in[8];
    const float* b1      = (const float*)d_in[9];
    const float* g1      = (const float*)d_in[10];
    const float* be1     = (const float*)d_in[11];
    float* out = (float*)d_out;

    __nv_bfloat16 *p1h, *p1l, *p2h, *p2l;
    __nv_bfloat16 *w0ah, *w0al, *w0bh, *w0bl, *w1h, *w1l;
    float *zt, *y1, *y2, *p1s, *p1q, *p2s, *p2q, *a0, *c0, *a1, *c1;
    cudaGetSymbolAddress((void**)&p1h, g_P1h);  cudaGetSymbolAddress((void**)&p1l, g_P1l);
    cudaGetSymbolAddress((void**)&p2h, g_P2h);  cudaGetSymbolAddress((void**)&p2l, g_P2l);
    cudaGetSymbolAddress((void**)&w0ah, g_W0ah); cudaGetSymbolAddress((void**)&w0al, g_W0al);
    cudaGetSymbolAddress((void**)&w0bh, g_W0bh); cudaGetSymbolAddress((void**)&w0bl, g_W0bl);
    cudaGetSymbolAddress((void**)&w1h, g_W1h);   cudaGetSymbolAddress((void**)&w1l, g_W1l);
    cudaGetSymbolAddress((void**)&zt, g_Zt);
    cudaGetSymbolAddress((void**)&y1, g_Y1);     cudaGetSymbolAddress((void**)&y2, g_Y2);
    cudaGetSymbolAddress((void**)&p1s, g_p1s);   cudaGetSymbolAddress((void**)&p1q, g_p1q);
    cudaGetSymbolAddress((void**)&p2s, g_p2s);   cudaGetSymbolAddress((void**)&p2q, g_p2q);
    cudaGetSymbolAddress((void**)&a0, g_a0);     cudaGetSymbolAddress((void**)&c0, g_c0);
    cudaGetSymbolAddress((void**)&a1, g_a1);     cudaGetSymbolAddress((void**)&c1, g_c1);

    const int SMEM = 2 * BUFSZ + 1536 + 1536 + 2048;    // 87040
    cudaFuncSetAttribute(gemm_mma<C1, D2C, 0, SPTS>, cudaFuncAttributeMaxDynamicSharedMemorySize, SMEM);
    cudaFuncSetAttribute(gemm_mma<C1, D1C, 1, NPTS>, cudaFuncAttributeMaxDynamicSharedMemorySize, SMEM);
    cudaFuncSetAttribute(gemm_y2, cudaFuncAttributeMaxDynamicSharedMemorySize, SMEM);

    // lazy-init side streams + events (created on the non-captured
    // correctness call; reused identically on every call)
    static cudaStream_t s_knn = nullptr, s_p1 = nullptr;
    static cudaEvent_t  ev_fork = nullptr, ev_knn = nullptr, ev_p1 = nullptr;
    if (s_knn == nullptr) {
        cudaStreamCreateWithFlags(&s_knn, cudaStreamNonBlocking);
        cudaStreamCreateWithFlags(&s_p1, cudaStreamNonBlocking);
        cudaEventCreateWithFlags(&ev_fork, cudaEventDisableTiming);
        cudaEventCreateWithFlags(&ev_knn, cudaEventDisableTiming);
        cudaEventCreateWithFlags(&ev_p1, cudaEventDisableTiming);
    }

    // fork
    cudaEventRecord(ev_fork, 0);
    cudaStreamWaitEvent(s_knn, ev_fork, 0);
    cudaStreamWaitEvent(s_p1, ev_fork, 0);

    // stream K: knn chain
    knn_part<<<dim3(NPTS / 256, BB, SSPLIT), 256, 0, s_knn>>>(xyz1, xyz2);
    knn_merge<<<BB * NPTS / 256, 256, 0, s_knn>>>();
    cudaEventRecord(ev_knn, s_knn);

    // stream P: points1 transpose/split (only needed by gemm_y1)
    conv_t<D1C, NPTS><<<dim3(NPTS / 32, D1C / 64, BB), dim3(32, 8), 0, s_p1>>>(points1, p1h, p1l);
    cudaEventRecord(ev_p1, s_p1);

    // stream 0: weight split -> points2 split -> Zt GEMM
    conv_w<<<(C1 * INCH + C2 * C1 + 255) / 256, 256>>>(W0, W1);
    conv_t<D2C, SPTS><<<dim3(SPTS / 32, D2C / 64, BB), dim3(32, 8)>>>(points2, p2h, p2l);
    gemm_mma<C1, D2C, 0, SPTS><<<dim3(SPTS / 128, BB, 2), 256, SMEM>>>(
        p2h, p2l, w0bh, w0bl, nullptr, zt, nullptr, nullptr);

    // join: gemm_y1 needs Zt, knn results, and points1 splits
    cudaStreamWaitEvent(0, ev_knn, 0);
    cudaStreamWaitEvent(0, ev_p1, 0);
    gemm_mma<C1, D1C, 1, NPTS><<<dim3(NPTS / 128, BB, 2), 256, SMEM>>>(
        p1h, p1l, w0ah, w0al, b0, y1, p1s, p1q);

    reduce_fin<<<C1, 256>>>(p1s, p1q, g0, be0, a0, c0);

    gemm_y2<<<dim3(NPTS / 128, BB), 256, SMEM>>>(y1, w1h, w1l, b1, y2, p2s, p2q);

    reduce_fin<<<C2, 256>>>(p2s, p2q, g1, be1, a1, c1);
    apply2<<<dim3(NPTS / 32, C2 / 32, BB), dim3(32, 8)>>>(out);
}